// round 1
// baseline (speedup 1.0000x reference)
#include <cuda_runtime.h>

#define LQ 1024   // sequence length H*W
// Shapes: B=8, C=512, heads=8, ch=64, groups=32 (16 ch/group)

// Scratch (device globals: no allocation allowed in kernel_launch)
__device__ float g_gn  [(size_t)8 * 512  * 1024];   // 16 MB  groupnorm output
__device__ float g_qkv [(size_t)8 * 1536 * 1024];   // 48 MB  qkv activations
__device__ float g_S   [(size_t)64 * 1024 * 1024];  // 256 MB attention scores / probs
__device__ float g_attn[(size_t)8 * 512  * 1024];   // 16 MB  attention output

// ---------------------------------------------------------------------------
// GroupNorm: one block per (batch, group). Group = 16 channels x 1024 = 16384.
// ---------------------------------------------------------------------------
__global__ void gn_kernel(const float* __restrict__ x, const float* __restrict__ w,
                          const float* __restrict__ bb, float* __restrict__ out)
{
    int b = blockIdx.x >> 5;
    int g = blockIdx.x & 31;
    const float4* xp = (const float4*)(x  + ((size_t)b * 512 + g * 16) * LQ);
    float4*       op = (float4*)      (out + ((size_t)b * 512 + g * 16) * LQ);
    int tid = threadIdx.x;  // 256 threads

    float s = 0.f, ss = 0.f;
    float4 vals[16];
#pragma unroll
    for (int i = 0; i < 16; i++) {
        float4 v = xp[tid + i * 256];
        vals[i] = v;
        s  += v.x + v.y + v.z + v.w;
        ss += v.x * v.x + v.y * v.y + v.z * v.z + v.w * v.w;
    }
    __shared__ float rs[8], rss[8];
#pragma unroll
    for (int o = 16; o > 0; o >>= 1) {
        s  += __shfl_xor_sync(0xffffffffu, s, o);
        ss += __shfl_xor_sync(0xffffffffu, ss, o);
    }
    if ((tid & 31) == 0) { rs[tid >> 5] = s; rss[tid >> 5] = ss; }
    __syncthreads();
    float S = 0.f, SS = 0.f;
#pragma unroll
    for (int i = 0; i < 8; i++) { S += rs[i]; SS += rss[i]; }
    float mean = S * (1.f / 16384.f);
    float var  = SS * (1.f / 16384.f) - mean * mean;
    float inv  = rsqrtf(var + 1e-5f);
#pragma unroll
    for (int i = 0; i < 16; i++) {
        int idx = tid + i * 256;
        int c   = idx >> 8;               // 256 float4 per channel
        float wc = w[g * 16 + c] * inv;
        float bc = bb[g * 16 + c] - mean * wc;
        float4 v = vals[i];
        v.x = v.x * wc + bc; v.y = v.y * wc + bc;
        v.z = v.z * wc + bc; v.w = v.w * wc + bc;
        op[idx] = v;
    }
}

// ---------------------------------------------------------------------------
// 128x128x8 register-blocked SGEMM:  out[b] = A(MxK) * X[b](Kx1024) + bias (+res)
// grid = (M/128, 1024/128, B), 256 threads, 8x8 per thread.
// ---------------------------------------------------------------------------
__global__ void gemm128_kernel(const float* __restrict__ A, const float* __restrict__ B,
                               const float* __restrict__ bias, const float* __restrict__ res,
                               float* __restrict__ out, int K, int doRes)
{
    int bz = blockIdx.z;
    const float* Bp = B + (size_t)bz * K * LQ;
    float*       Op = out + (size_t)bz * gridDim.x * 128 * LQ;
    const float* Rp = doRes ? (res + (size_t)bz * gridDim.x * 128 * LQ) : nullptr;

    __shared__ float As[8][128];
    __shared__ float Bs[8][128];

    int tid = threadIdx.x;
    int tx = tid & 15, ty = tid >> 4;
    int m0 = blockIdx.x * 128, n0 = blockIdx.y * 128;

    int a_row = tid >> 1;
    int a_col = (tid & 1) * 4;
    int b_row = tid >> 5;
    int b_col = (tid & 31) * 4;

    const float* Aptr = A  + (size_t)(m0 + a_row) * K + a_col;
    const float* Bptr = Bp + (size_t)b_row * LQ + n0 + b_col;

    float acc[8][8] = {};
    for (int k0 = 0; k0 < K; k0 += 8) {
        float4 av = *(const float4*)(Aptr + k0);
        As[a_col + 0][a_row] = av.x;
        As[a_col + 1][a_row] = av.y;
        As[a_col + 2][a_row] = av.z;
        As[a_col + 3][a_row] = av.w;
        *(float4*)&Bs[b_row][b_col] = *(const float4*)(Bptr + (size_t)k0 * LQ);
        __syncthreads();
#pragma unroll
        for (int kk = 0; kk < 8; kk++) {
            float ar[8], br[8];
#pragma unroll
            for (int i = 0; i < 8; i++) ar[i] = As[kk][ty * 8 + i];
#pragma unroll
            for (int j = 0; j < 8; j++) br[j] = Bs[kk][tx * 8 + j];
#pragma unroll
            for (int i = 0; i < 8; i++)
#pragma unroll
                for (int j = 0; j < 8; j++)
                    acc[i][j] += ar[i] * br[j];
        }
        __syncthreads();
    }
#pragma unroll
    for (int i = 0; i < 8; i++) {
        int m = m0 + ty * 8 + i;
        float bv = bias[m];
        size_t base = (size_t)m * LQ + n0 + tx * 8;
#pragma unroll
        for (int j = 0; j < 8; j++) {
            float v = acc[i][j] + bv;
            if (doRes) v += Rp[base + j];
            Op[base + j] = v;
        }
    }
}

// ---------------------------------------------------------------------------
// Scores: S[t][s] = (1/8) * sum_c q[c][t] * k[c][s]
// grid = (8 t-tiles, 8 s-tiles, 64 bh), 128x128 tile, K=64 (chunks of 32).
// ---------------------------------------------------------------------------
__global__ void scores_kernel(const float* __restrict__ qkv, float* __restrict__ S)
{
    int bh = blockIdx.z;
    int b = bh >> 3, h = bh & 7;
    const float* q = qkv + ((size_t)b * 1536 + h * 192) * LQ;
    const float* k = q + (size_t)64 * LQ;

    __shared__ float Qs[32][128];
    __shared__ float Ks[32][128];

    int tid = threadIdx.x;
    int tx = tid & 15, ty = tid >> 4;
    int t0 = blockIdx.x * 128, s0 = blockIdx.y * 128;

    float acc[8][8] = {};
    for (int c0 = 0; c0 < 64; c0 += 32) {
#pragma unroll
        for (int i = 0; i < 4; i++) {
            int idx = tid + i * 256;
            int c   = idx >> 5;
            int col = (idx & 31) * 4;
            *(float4*)&Qs[c][col] = *(const float4*)(q + (size_t)(c0 + c) * LQ + t0 + col);
            *(float4*)&Ks[c][col] = *(const float4*)(k + (size_t)(c0 + c) * LQ + s0 + col);
        }
        __syncthreads();
#pragma unroll
        for (int kk = 0; kk < 32; kk++) {
            float ar[8], br[8];
#pragma unroll
            for (int i = 0; i < 8; i++) ar[i] = Qs[kk][ty * 8 + i];
#pragma unroll
            for (int j = 0; j < 8; j++) br[j] = Ks[kk][tx * 8 + j];
#pragma unroll
            for (int i = 0; i < 8; i++)
#pragma unroll
                for (int j = 0; j < 8; j++)
                    acc[i][j] += ar[i] * br[j];
        }
        __syncthreads();
    }
    float* Sp = S + (size_t)bh * LQ * LQ;
#pragma unroll
    for (int i = 0; i < 8; i++) {
        size_t base = (size_t)(t0 + ty * 8 + i) * LQ + s0 + tx * 8;
#pragma unroll
        for (int j = 0; j < 8; j++)
            Sp[base + j] = acc[i][j] * 0.125f;
    }
}

// ---------------------------------------------------------------------------
// Row softmax over 1024 elements. grid = 64*1024 rows, 256 threads (1 float4 each).
// ---------------------------------------------------------------------------
__global__ void softmax_kernel(float* __restrict__ S)
{
    size_t row = blockIdx.x;
    float4* p = (float4*)(S + row * LQ);
    int tid = threadIdx.x;
    float4 v = p[tid];

    __shared__ float rmax[8], rsum[8];
    float m = fmaxf(fmaxf(v.x, v.y), fmaxf(v.z, v.w));
#pragma unroll
    for (int o = 16; o > 0; o >>= 1)
        m = fmaxf(m, __shfl_xor_sync(0xffffffffu, m, o));
    if ((tid & 31) == 0) rmax[tid >> 5] = m;
    __syncthreads();
    float M = -1e30f;
#pragma unroll
    for (int i = 0; i < 8; i++) M = fmaxf(M, rmax[i]);

    v.x = __expf(v.x - M); v.y = __expf(v.y - M);
    v.z = __expf(v.z - M); v.w = __expf(v.w - M);
    float s = v.x + v.y + v.z + v.w;
#pragma unroll
    for (int o = 16; o > 0; o >>= 1)
        s += __shfl_xor_sync(0xffffffffu, s, o);
    if ((tid & 31) == 0) rsum[tid >> 5] = s;
    __syncthreads();
    float Z = 0.f;
#pragma unroll
    for (int i = 0; i < 8; i++) Z += rsum[i];
    float inv = 1.f / Z;
    v.x *= inv; v.y *= inv; v.z *= inv; v.w *= inv;
    p[tid] = v;
}

// ---------------------------------------------------------------------------
// A[c][t] = sum_s P[t][s] * v[c][s].  BM=64 (c), BN=128 (t), BK=32 (s).
// grid = (8 t-tiles, 1, 64 bh), 256 threads, 4x8 per thread.
// ---------------------------------------------------------------------------
__global__ void av_kernel(const float* __restrict__ qkv, const float* __restrict__ P,
                          float* __restrict__ Aout)
{
    int bh = blockIdx.z;
    int b = bh >> 3, h = bh & 7;
    const float* v  = qkv + ((size_t)b * 1536 + h * 192 + 128) * LQ;
    const float* Pp = P + (size_t)bh * LQ * LQ;
    float*       Ap = Aout + ((size_t)b * 512 + h * 64) * LQ;

    __shared__ float Vs[32][65];    // [s][c]
    __shared__ float Ps[32][129];   // [s][t]

    int tid = threadIdx.x;
    int tx = tid & 15, ty = tid >> 4;
    int n0 = blockIdx.x * 128;

    float acc[4][8] = {};
    for (int s0 = 0; s0 < LQ; s0 += 32) {
#pragma unroll
        for (int i = 0; i < 2; i++) {
            int idx = tid + i * 256;           // float4 over 64(c) x 8(f4 of s)
            int c   = idx >> 3;
            int s4  = (idx & 7) * 4;
            float4 vv = *(const float4*)(v + (size_t)c * LQ + s0 + s4);
            Vs[s4 + 0][c] = vv.x; Vs[s4 + 1][c] = vv.y;
            Vs[s4 + 2][c] = vv.z; Vs[s4 + 3][c] = vv.w;
        }
#pragma unroll
        for (int i = 0; i < 4; i++) {
            int idx = tid + i * 256;           // float4 over 128(t) x 8(f4 of s)
            int t   = idx >> 3;
            int s4  = (idx & 7) * 4;
            float4 pv = *(const float4*)(Pp + (size_t)(n0 + t) * LQ + s0 + s4);
            Ps[s4 + 0][t] = pv.x; Ps[s4 + 1][t] = pv.y;
            Ps[s4 + 2][t] = pv.z; Ps[s4 + 3][t] = pv.w;
        }
        __syncthreads();
#pragma unroll
        for (int kk = 0; kk < 32; kk++) {
            float ar[4], br[8];
#pragma unroll
            for (int i = 0; i < 4; i++) ar[i] = Vs[kk][ty * 4 + i];
#pragma unroll
            for (int j = 0; j < 8; j++) br[j] = Ps[kk][tx * 8 + j];
#pragma unroll
            for (int i = 0; i < 4; i++)
#pragma unroll
                for (int j = 0; j < 8; j++)
                    acc[i][j] += ar[i] * br[j];
        }
        __syncthreads();
    }
#pragma unroll
    for (int i = 0; i < 4; i++) {
        size_t base = (size_t)(ty * 4 + i) * LQ + n0 + tx * 8;
#pragma unroll
        for (int j = 0; j < 8; j++)
            Ap[base + j] = acc[i][j];
    }
}

// ---------------------------------------------------------------------------
extern "C" void kernel_launch(void* const* d_in, const int* in_sizes, int n_in,
                              void* d_out, int out_size)
{
    const float* x      = (const float*)d_in[0];
    const float* gn_w   = (const float*)d_in[1];
    const float* gn_b   = (const float*)d_in[2];
    const float* qkv_w  = (const float*)d_in[3];
    const float* qkv_b  = (const float*)d_in[4];
    const float* proj_w = (const float*)d_in[5];
    const float* proj_b = (const float*)d_in[6];
    float* out = (float*)d_out;

    float *gn, *qkvb, *Sb, *attn;
    cudaGetSymbolAddress((void**)&gn,   g_gn);
    cudaGetSymbolAddress((void**)&qkvb, g_qkv);
    cudaGetSymbolAddress((void**)&Sb,   g_S);
    cudaGetSymbolAddress((void**)&attn, g_attn);

    // 1. GroupNorm
    gn_kernel<<<256, 256>>>(x, gn_w, gn_b, gn);
    // 2. QKV GEMM: (1536x512) x (8 x 512x1024)
    gemm128_kernel<<<dim3(12, 8, 8), 256>>>(qkv_w, gn, qkv_b, nullptr, qkvb, 512, 0);
    // 3. Scores S = (Q^T K)/8 per (b,h)
    scores_kernel<<<dim3(8, 8, 64), 256>>>(qkvb, Sb);
    // 4. Row softmax
    softmax_kernel<<<64 * 1024, 256>>>(Sb);
    // 5. A = V * P^T
    av_kernel<<<dim3(8, 1, 64), 256>>>(qkvb, Sb, attn);
    // 6. proj GEMM + bias + residual
    gemm128_kernel<<<dim3(4, 8, 8), 256>>>(proj_w, attn, proj_b, x, out, 512, 1);
}

// round 3
// speedup vs baseline: 1.5159x; 1.5159x over previous
#include <cuda_runtime.h>
#include <cuda_bf16.h>
#include <cstdint>

#define LQ 1024
// B=8, C=512, heads=8/batch (bh=64), ch=64, groups=32

// ---------------------------------------------------------------------------
// Scratch
// ---------------------------------------------------------------------------
__device__ float g_gn  [(size_t)8 * 512  * 1024];    // [b][c][l]
__device__ float g_gnT [(size_t)8 * 1024 * 512];     // [b][l][c]
__device__ float g_qkvT[(size_t)8 * 1024 * 1536];    // [b][l][o]
__device__ float g_S   [(size_t)64 * 1024 * 1024];   // [bh][t][s] scores then probs
__device__ float g_v   [(size_t)64 * 64 * 1024];     // [bh][c][s]
__device__ float g_aT  [(size_t)8 * 1024 * 512];     // [b][l][c]

// ---------------------------------------------------------------------------
// bf16 split helpers + mma.sync wrapper (valid on any sm_80+ target)
// ---------------------------------------------------------------------------
__device__ __forceinline__ void split2(float2 f, uint32_t& hi, uint32_t& lo)
{
    __nv_bfloat162 h = __float22bfloat162_rn(f);
    float2 rem = make_float2(f.x - __bfloat162float(h.x),
                             f.y - __bfloat162float(h.y));
    __nv_bfloat162 l = __float22bfloat162_rn(rem);
    hi = *reinterpret_cast<uint32_t*>(&h);
    lo = *reinterpret_cast<uint32_t*>(&l);
}

__device__ __forceinline__ void mma16816(float* c, const uint32_t* a, const uint32_t* b)
{
    asm volatile(
        "mma.sync.aligned.m16n8k16.row.col.f32.bf16.bf16.f32 "
        "{%0,%1,%2,%3}, {%4,%5,%6,%7}, {%8,%9}, {%0,%1,%2,%3};"
        : "+f"(c[0]), "+f"(c[1]), "+f"(c[2]), "+f"(c[3])
        : "r"(a[0]), "r"(a[1]), "r"(a[2]), "r"(a[3]), "r"(b[0]), "r"(b[1]));
}

// ---------------------------------------------------------------------------
// Core: acc[MT][NT][4] += A(BM x K, row-major lda) * B(BN x K, row-major ldb)^T
// fp32 inputs, bf16 hi/lo 3-product mma. BK=32, padded smem stride 36.
// 256 threads. Warp grid: (BM/WM) x (BN/WN), warp tile WM x WN.
// ---------------------------------------------------------------------------
template<int BM, int BN, int WM, int WN>
__device__ __forceinline__ void gemm_core(
    const float* __restrict__ Ag, int lda,
    const float* __restrict__ Bg, int ldb,
    int K, float* smem, float (*acc)[WN / 8][4])
{
    constexpr int BKP = 36;
    constexpr int MT = WM / 16, NT = WN / 8;
    constexpr int WARPS_N = BN / WN;
    float* As = smem;
    float* Bs = smem + BM * BKP;

    const int tid  = threadIdx.x;
    const int lane = tid & 31, warp = tid >> 5;
    const int wm = (warp / WARPS_N) * WM;
    const int wn = (warp % WARPS_N) * WN;
    const int g  = lane >> 2, t2 = (lane & 3) * 2;

    for (int k0 = 0; k0 < K; k0 += 32) {
#pragma unroll
        for (int i = tid; i < BM * 8; i += 256) {
            int r = i >> 3, c4 = (i & 7) * 4;
            *(float4*)&As[r * BKP + c4] = *(const float4*)(Ag + (size_t)r * lda + k0 + c4);
        }
#pragma unroll
        for (int i = tid; i < BN * 8; i += 256) {
            int r = i >> 3, c4 = (i & 7) * 4;
            *(float4*)&Bs[r * BKP + c4] = *(const float4*)(Bg + (size_t)r * ldb + k0 + c4);
        }
        __syncthreads();
#pragma unroll
        for (int kk = 0; kk < 32; kk += 16) {
            uint32_t ahi[MT][4], alo[MT][4], bhi[NT][2], blo[NT][2];
#pragma unroll
            for (int im = 0; im < MT; im++) {
                const float* r0 = &As[(wm + im * 16 + g) * BKP + kk + t2];
                const float* r1 = r0 + 8 * BKP;
                split2(*(const float2*)(r0),     ahi[im][0], alo[im][0]);
                split2(*(const float2*)(r1),     ahi[im][1], alo[im][1]);
                split2(*(const float2*)(r0 + 8), ahi[im][2], alo[im][2]);
                split2(*(const float2*)(r1 + 8), ahi[im][3], alo[im][3]);
            }
#pragma unroll
            for (int in = 0; in < NT; in++) {
                const float* c0 = &Bs[(wn + in * 8 + g) * BKP + kk + t2];
                split2(*(const float2*)(c0),     bhi[in][0], blo[in][0]);
                split2(*(const float2*)(c0 + 8), bhi[in][1], blo[in][1]);
            }
#pragma unroll
            for (int im = 0; im < MT; im++)
#pragma unroll
                for (int in = 0; in < NT; in++) {
                    mma16816(acc[im][in], ahi[im], bhi[in]);
                    mma16816(acc[im][in], ahi[im], blo[in]);
                    mma16816(acc[im][in], alo[im], bhi[in]);
                }
        }
        __syncthreads();
    }
}

// ---------------------------------------------------------------------------
// Stage kernels
// ---------------------------------------------------------------------------
// qkvT[b][l][o] = gnT[b][l][:] . W[o][:] + bias[o]
__global__ __launch_bounds__(256)
void qkv_mma(const float* __restrict__ gnT, const float* __restrict__ W,
             const float* __restrict__ bias, float* __restrict__ qkvT)
{
    __shared__ float smem[2 * 128 * 36];
    float acc[4][4][4] = {};
    const int m0 = blockIdx.x * 128, n0 = blockIdx.y * 128, b = blockIdx.z;
    gemm_core<128, 128, 64, 32>(gnT + ((size_t)b * 1024 + m0) * 512, 512,
                                W + (size_t)n0 * 512, 512, 512, smem, acc);
    const int lane = threadIdx.x & 31, warp = threadIdx.x >> 5;
    const int wm = (warp / 4) * 64, wn = (warp % 4) * 32;
    const int g = lane >> 2, t2 = (lane & 3) * 2;
    float* outB = qkvT + (size_t)b * 1024 * 1536;
#pragma unroll
    for (int in = 0; in < 4; in++) {
        const int c = n0 + wn + in * 8 + t2;
        const float bx = bias[c], by = bias[c + 1];
#pragma unroll
        for (int im = 0; im < 4; im++) {
            const int r = m0 + wm + im * 16 + g;
            *(float2*)(outB + (size_t)r * 1536 + c) =
                make_float2(acc[im][in][0] + bx, acc[im][in][1] + by);
            *(float2*)(outB + (size_t)(r + 8) * 1536 + c) =
                make_float2(acc[im][in][2] + bx, acc[im][in][3] + by);
        }
    }
}

// S[bh][t][s] = 0.125 * q[t][:] . k[s][:]   (q,k strided views of qkvT)
__global__ __launch_bounds__(256)
void scores_mma(const float* __restrict__ qkvT, float* __restrict__ S)
{
    __shared__ float smem[2 * 128 * 36];
    float acc[4][4][4] = {};
    const int t0 = blockIdx.x * 128, s0 = blockIdx.y * 128, bh = blockIdx.z;
    const int b = bh >> 3, h = bh & 7;
    const float* base = qkvT + (size_t)b * 1024 * 1536 + h * 192;
    gemm_core<128, 128, 64, 32>(base + (size_t)t0 * 1536, 1536,
                                base + 64 + (size_t)s0 * 1536, 1536, 64, smem, acc);
    const int lane = threadIdx.x & 31, warp = threadIdx.x >> 5;
    const int wm = (warp / 4) * 64, wn = (warp % 4) * 32;
    const int g = lane >> 2, t2 = (lane & 3) * 2;
    float* Sp = S + ((size_t)bh << 20);
#pragma unroll
    for (int im = 0; im < 4; im++) {
        const int r = t0 + wm + im * 16 + g;
#pragma unroll
        for (int in = 0; in < 4; in++) {
            const int c = s0 + wn + in * 8 + t2;
            *(float2*)(Sp + (size_t)r * 1024 + c) =
                make_float2(acc[im][in][0] * 0.125f, acc[im][in][1] * 0.125f);
            *(float2*)(Sp + (size_t)(r + 8) * 1024 + c) =
                make_float2(acc[im][in][2] * 0.125f, acc[im][in][3] * 0.125f);
        }
    }
}

// aT[b][t][h*64+c] = P[t][:] . v[c][:]
__global__ __launch_bounds__(256)
void av_mma(const float* __restrict__ P, const float* __restrict__ v,
            float* __restrict__ aT)
{
    __shared__ float smem[(128 + 64) * 36];
    float acc[2][4][4] = {};
    const int t0 = blockIdx.x * 128, bh = blockIdx.z;
    const int b = bh >> 3, h = bh & 7;
    gemm_core<128, 64, 32, 32>(P + ((size_t)bh << 20) + (size_t)t0 * 1024, 1024,
                               v + ((size_t)bh << 16), 1024, 1024, smem, acc);
    const int lane = threadIdx.x & 31, warp = threadIdx.x >> 5;
    const int wm = (warp / 2) * 32, wn = (warp % 2) * 32;
    const int g = lane >> 2, t2 = (lane & 3) * 2;
    float* outB = aT + (size_t)b * 1024 * 512 + h * 64;
#pragma unroll
    for (int im = 0; im < 2; im++) {
        const int r = t0 + wm + im * 16 + g;
#pragma unroll
        for (int in = 0; in < 4; in++) {
            const int c = wn + in * 8 + t2;
            *(float2*)(outB + (size_t)r * 512 + c) =
                make_float2(acc[im][in][0], acc[im][in][1]);
            *(float2*)(outB + (size_t)(r + 8) * 512 + c) =
                make_float2(acc[im][in][2], acc[im][in][3]);
        }
    }
}

// out[b][co][l] = x[b][co][l] + projW[co][:] . aT[b][l][:] + bias[co]
__global__ __launch_bounds__(256)
void proj_mma(const float* __restrict__ W, const float* __restrict__ aT,
              const float* __restrict__ bias, const float* __restrict__ x,
              float* __restrict__ out)
{
    __shared__ float smem[2 * 128 * 36];
    float acc[4][4][4] = {};
    const int m0 = blockIdx.x * 128, n0 = blockIdx.y * 128, b = blockIdx.z;
    gemm_core<128, 128, 64, 32>(W + (size_t)m0 * 512, 512,
                                aT + ((size_t)b * 1024 + n0) * 512, 512, 512, smem, acc);
    const int lane = threadIdx.x & 31, warp = threadIdx.x >> 5;
    const int wm = (warp / 4) * 64, wn = (warp % 4) * 32;
    const int g = lane >> 2, t2 = (lane & 3) * 2;
    const size_t bb = (size_t)b * 512 * 1024;
#pragma unroll
    for (int im = 0; im < 4; im++) {
        const int r = m0 + wm + im * 16 + g;
        const float bv0 = bias[r], bv1 = bias[r + 8];
#pragma unroll
        for (int in = 0; in < 4; in++) {
            const int c = n0 + wn + in * 8 + t2;
            size_t o0 = bb + (size_t)r * 1024 + c;
            size_t o1 = bb + (size_t)(r + 8) * 1024 + c;
            float2 x0 = *(const float2*)(x + o0);
            float2 x1 = *(const float2*)(x + o1);
            *(float2*)(out + o0) = make_float2(acc[im][in][0] + bv0 + x0.x,
                                               acc[im][in][1] + bv0 + x0.y);
            *(float2*)(out + o1) = make_float2(acc[im][in][2] + bv1 + x1.x,
                                               acc[im][in][3] + bv1 + x1.y);
        }
    }
}

// ---------------------------------------------------------------------------
// GroupNorm (unchanged from R1)
// ---------------------------------------------------------------------------
__global__ void gn_kernel(const float* __restrict__ x, const float* __restrict__ w,
                          const float* __restrict__ bb, float* __restrict__ out)
{
    int b = blockIdx.x >> 5;
    int g = blockIdx.x & 31;
    const float4* xp = (const float4*)(x  + ((size_t)b * 512 + g * 16) * LQ);
    float4*       op = (float4*)      (out + ((size_t)b * 512 + g * 16) * LQ);
    int tid = threadIdx.x;

    float s = 0.f, ss = 0.f;
    float4 vals[16];
#pragma unroll
    for (int i = 0; i < 16; i++) {
        float4 v = xp[tid + i * 256];
        vals[i] = v;
        s  += v.x + v.y + v.z + v.w;
        ss += v.x * v.x + v.y * v.y + v.z * v.z + v.w * v.w;
    }
    __shared__ float rs[8], rss[8];
#pragma unroll
    for (int o = 16; o > 0; o >>= 1) {
        s  += __shfl_xor_sync(0xffffffffu, s, o);
        ss += __shfl_xor_sync(0xffffffffu, ss, o);
    }
    if ((tid & 31) == 0) { rs[tid >> 5] = s; rss[tid >> 5] = ss; }
    __syncthreads();
    float S = 0.f, SS = 0.f;
#pragma unroll
    for (int i = 0; i < 8; i++) { S += rs[i]; SS += rss[i]; }
    float mean = S * (1.f / 16384.f);
    float var  = SS * (1.f / 16384.f) - mean * mean;
    float inv  = rsqrtf(var + 1e-5f);
#pragma unroll
    for (int i = 0; i < 16; i++) {
        int idx = tid + i * 256;
        int c   = idx >> 8;
        float wc = w[g * 16 + c] * inv;
        float bc = bb[g * 16 + c] - mean * wc;
        float4 v = vals[i];
        v.x = v.x * wc + bc; v.y = v.y * wc + bc;
        v.z = v.z * wc + bc; v.w = v.w * wc + bc;
        op[idx] = v;
    }
}

// Generic fp32 transpose: dst[c][r] = src[r][c]. grid(x=C/32, y=R/32, z=batch)
__global__ void transpose_kernel(const float* __restrict__ src, float* __restrict__ dst,
                                 int sld, int dld, size_t sstride, size_t dstride)
{
    __shared__ float t[32][33];
    const float* s = src + (size_t)blockIdx.z * sstride;
    float*       d = dst + (size_t)blockIdx.z * dstride;
    int r0 = blockIdx.y * 32, c0 = blockIdx.x * 32;
    int x = threadIdx.x, y = threadIdx.y;
#pragma unroll
    for (int k = 0; k < 32; k += 8)
        t[y + k][x] = s[(size_t)(r0 + y + k) * sld + c0 + x];
    __syncthreads();
#pragma unroll
    for (int k = 0; k < 32; k += 8)
        d[(size_t)(c0 + y + k) * dld + r0 + x] = t[x][y + k];
}

// v[bh][c][s] = qkvT[b][s][h*192+128+c]
__global__ void vtrans_kernel(const float* __restrict__ qkvT, float* __restrict__ v)
{
    __shared__ float t[32][33];
    int bh = blockIdx.z, b = bh >> 3, h = bh & 7;
    const float* s = qkvT + (size_t)b * 1024 * 1536 + h * 192 + 128;
    float*       d = v + ((size_t)bh << 16);
    int s0 = blockIdx.x * 32, c0 = blockIdx.y * 32;
    int x = threadIdx.x, y = threadIdx.y;
#pragma unroll
    for (int k = 0; k < 32; k += 8)
        t[y + k][x] = s[(size_t)(s0 + y + k) * 1536 + c0 + x];
    __syncthreads();
#pragma unroll
    for (int k = 0; k < 32; k += 8)
        d[(size_t)(c0 + y + k) * 1024 + s0 + x] = t[x][y + k];
}

// In-place row softmax over 1024
__global__ void softmax_kernel(float* __restrict__ S)
{
    size_t row = blockIdx.x;
    float4* p = (float4*)(S + row * LQ);
    int tid = threadIdx.x;
    float4 v = p[tid];

    __shared__ float rmax[8], rsum[8];
    float m = fmaxf(fmaxf(v.x, v.y), fmaxf(v.z, v.w));
#pragma unroll
    for (int o = 16; o > 0; o >>= 1)
        m = fmaxf(m, __shfl_xor_sync(0xffffffffu, m, o));
    if ((tid & 31) == 0) rmax[tid >> 5] = m;
    __syncthreads();
    float M = -1e30f;
#pragma unroll
    for (int i = 0; i < 8; i++) M = fmaxf(M, rmax[i]);

    v.x = __expf(v.x - M); v.y = __expf(v.y - M);
    v.z = __expf(v.z - M); v.w = __expf(v.w - M);
    float s = v.x + v.y + v.z + v.w;
#pragma unroll
    for (int o = 16; o > 0; o >>= 1)
        s += __shfl_xor_sync(0xffffffffu, s, o);
    if ((tid & 31) == 0) rsum[tid >> 5] = s;
    __syncthreads();
    float Z = 0.f;
#pragma unroll
    for (int i = 0; i < 8; i++) Z += rsum[i];
    float inv = 1.f / Z;
    v.x *= inv; v.y *= inv; v.z *= inv; v.w *= inv;
    p[tid] = v;
}

// ---------------------------------------------------------------------------
extern "C" void kernel_launch(void* const* d_in, const int* in_sizes, int n_in,
                              void* d_out, int out_size)
{
    const float* x      = (const float*)d_in[0];
    const float* gn_w   = (const float*)d_in[1];
    const float* gn_b   = (const float*)d_in[2];
    const float* qkv_w  = (const float*)d_in[3];
    const float* qkv_b  = (const float*)d_in[4];
    const float* proj_w = (const float*)d_in[5];
    const float* proj_b = (const float*)d_in[6];
    float* out = (float*)d_out;

    float *gn, *gnT, *qkvT, *Sb, *vb, *aT;
    cudaGetSymbolAddress((void**)&gn,   g_gn);
    cudaGetSymbolAddress((void**)&gnT,  g_gnT);
    cudaGetSymbolAddress((void**)&qkvT, g_qkvT);
    cudaGetSymbolAddress((void**)&Sb,   g_S);
    cudaGetSymbolAddress((void**)&vb,   g_v);
    cudaGetSymbolAddress((void**)&aT,   g_aT);

    // 1. GroupNorm -> gn [b][c][l]
    gn_kernel<<<256, 256>>>(x, gn_w, gn_b, gn);
    // 2. gn -> gnT [b][l][c]
    transpose_kernel<<<dim3(32, 16, 8), dim3(32, 8)>>>(gn, gnT, 1024, 512,
                                                       (size_t)512 * 1024, (size_t)1024 * 512);
    // 3. qkvT[b][l][o] = gnT . W^T + bias
    qkv_mma<<<dim3(8, 12, 8), 256>>>(gnT, qkv_w, qkv_b, qkvT);
    // 4. v[bh][c][s]
    vtrans_kernel<<<dim3(32, 2, 64), dim3(32, 8)>>>(qkvT, vb);
    // 5. S = (q . k^T)/8
    scores_mma<<<dim3(8, 8, 64), 256>>>(qkvT, Sb);
    // 6. P = softmax(S) in-place
    softmax_kernel<<<65536, 256>>>(Sb);
    // 7. aT[b][l][c] = P . v^T
    av_mma<<<dim3(8, 1, 64), 256>>>(Sb, vb, aT);
    // 8. out = x + projW . aT^T + bias
    proj_mma<<<dim3(4, 8, 8), 256>>>(proj_w, aT, proj_b, x, out);
}

// round 5
// speedup vs baseline: 2.0310x; 1.3398x over previous
#include <cuda_runtime.h>
#include <cuda_bf16.h>
#include <cstdint>

#define LQ 1024
// B=8, C=512, heads=8/batch (bh=64), ch=64, groups=32

// ---------------------------------------------------------------------------
// Scratch
// ---------------------------------------------------------------------------
__device__ float g_gn  [(size_t)8 * 512  * 1024];    // [b][c][l]
__device__ float g_gnT [(size_t)8 * 1024 * 512];     // [b][l][c]
__device__ float g_qkvT[(size_t)8 * 1024 * 1536];    // [b][l][o]
__device__ float g_aT  [(size_t)8 * 1024 * 512];     // [b][l][c]

// ---------------------------------------------------------------------------
// bf16 split + mma.sync (portable PTX, any sm_80+ target)
// ---------------------------------------------------------------------------
__device__ __forceinline__ void split2(float2 f, uint32_t& hi, uint32_t& lo)
{
    __nv_bfloat162 h = __float22bfloat162_rn(f);
    float2 rem = make_float2(f.x - __bfloat162float(h.x),
                             f.y - __bfloat162float(h.y));
    __nv_bfloat162 l = __float22bfloat162_rn(rem);
    hi = *reinterpret_cast<uint32_t*>(&h);
    lo = *reinterpret_cast<uint32_t*>(&l);
}

__device__ __forceinline__ void mma16816(float* c, const uint32_t* a, const uint32_t* b)
{
    asm volatile(
        "mma.sync.aligned.m16n8k16.row.col.f32.bf16.bf16.f32 "
        "{%0,%1,%2,%3}, {%4,%5,%6,%7}, {%8,%9}, {%0,%1,%2,%3};"
        : "+f"(c[0]), "+f"(c[1]), "+f"(c[2]), "+f"(c[3])
        : "r"(a[0]), "r"(a[1]), "r"(a[2]), "r"(a[3]), "r"(b[0]), "r"(b[1]));
}

// ---------------------------------------------------------------------------
// Fused flash attention: per CTA = one (bh, 128-row t-tile).
// q,k,v are strided views of qkvT[b][l][h*192 + {0,64,128} + c].
// Output aT[b][t][h*64+c] (proj's B operand layout).
// 256 threads = 8 warps; warp w owns rows t0+16w .. t0+16w+15.
// ---------------------------------------------------------------------------
__global__ __launch_bounds__(256)
void flash_kernel(const float* __restrict__ qkvT, float* __restrict__ aT)
{
    constexpr int KP = 66;    // K smem row stride (bf16 units)
    constexpr int VP = 130;   // V^T smem row stride (bf16 units)
    extern __shared__ __nv_bfloat16 sm[];
    __nv_bfloat16* Khi = sm;
    __nv_bfloat16* Klo = Khi + 128 * KP;
    __nv_bfloat16* Vhi = Klo + 128 * KP;
    __nv_bfloat16* Vlo = Vhi + 64 * VP;

    const int tid = threadIdx.x, lane = tid & 31, warp = tid >> 5;
    const int g = lane >> 2, t2 = (lane & 3) * 2;
    const int t0 = blockIdx.x * 128, bh = blockIdx.y;
    const int b = bh >> 3, h = bh & 7;
    const float* base = qkvT + (size_t)b * 1024 * 1536 + h * 192;

    // --- Q fragments, held in registers for the whole kernel ---
    uint32_t qhi[4][4], qlo[4][4];
    {
        const int r0 = t0 + warp * 16 + g;
#pragma unroll
        for (int kc = 0; kc < 4; kc++) {
            const float* p0 = base + (size_t)r0 * 1536 + kc * 16 + t2;
            const float* p1 = p0 + 8 * 1536;
            split2(*(const float2*)p0,       qhi[kc][0], qlo[kc][0]);
            split2(*(const float2*)p1,       qhi[kc][1], qlo[kc][1]);
            split2(*(const float2*)(p0 + 8), qhi[kc][2], qlo[kc][2]);
            split2(*(const float2*)(p1 + 8), qhi[kc][3], qlo[kc][3]);
        }
    }

    float mrow0 = -1e30f, mrow1 = -1e30f, lrow0 = 0.f, lrow1 = 0.f;
    float O[8][4] = {};   // 8 n-tiles over 64 head cols

    for (int s0 = 0; s0 < LQ; s0 += 128) {
        if (s0) __syncthreads();
        // --- fill K (bf16 hi/lo, row-major [s][c]) and V^T ([c][s]) ---
#pragma unroll
        for (int j = 0; j < 8; j++) {
            int i = tid + j * 256;
            int r = i >> 4, c4 = (i & 15) * 4;
            const float* src = base + (size_t)(s0 + r) * 1536 + 64 + c4;
            float4 kv = *(const float4*)src;
            float4 vv = *(const float4*)(src + 64);
            __nv_bfloat16 kh0 = __float2bfloat16(kv.x);
            __nv_bfloat16 kh1 = __float2bfloat16(kv.y);
            __nv_bfloat16 kh2 = __float2bfloat16(kv.z);
            __nv_bfloat16 kh3 = __float2bfloat16(kv.w);
            __nv_bfloat16* kp = Khi + r * KP + c4;
            kp[0] = kh0; kp[1] = kh1; kp[2] = kh2; kp[3] = kh3;
            kp = Klo + r * KP + c4;
            kp[0] = __float2bfloat16(kv.x - __bfloat162float(kh0));
            kp[1] = __float2bfloat16(kv.y - __bfloat162float(kh1));
            kp[2] = __float2bfloat16(kv.z - __bfloat162float(kh2));
            kp[3] = __float2bfloat16(kv.w - __bfloat162float(kh3));
            __nv_bfloat16 vh0 = __float2bfloat16(vv.x);
            __nv_bfloat16 vh1 = __float2bfloat16(vv.y);
            __nv_bfloat16 vh2 = __float2bfloat16(vv.z);
            __nv_bfloat16 vh3 = __float2bfloat16(vv.w);
            Vhi[(c4 + 0) * VP + r] = vh0;
            Vhi[(c4 + 1) * VP + r] = vh1;
            Vhi[(c4 + 2) * VP + r] = vh2;
            Vhi[(c4 + 3) * VP + r] = vh3;
            Vlo[(c4 + 0) * VP + r] = __float2bfloat16(vv.x - __bfloat162float(vh0));
            Vlo[(c4 + 1) * VP + r] = __float2bfloat16(vv.y - __bfloat162float(vh1));
            Vlo[(c4 + 2) * VP + r] = __float2bfloat16(vv.z - __bfloat162float(vh2));
            Vlo[(c4 + 3) * VP + r] = __float2bfloat16(vv.w - __bfloat162float(vh3));
        }
        __syncthreads();

        // --- S = Q . K^T  (16 rows x 128 cols per warp) ---
        float S[16][4];
#pragma unroll
        for (int in = 0; in < 16; in++)
#pragma unroll
            for (int q = 0; q < 4; q++) S[in][q] = 0.f;
#pragma unroll
        for (int kc = 0; kc < 4; kc++) {
#pragma unroll
            for (int in = 0; in < 16; in++) {
                const int row = in * 8 + g;
                uint32_t bh2[2], bl2[2];
                bh2[0] = *(const uint32_t*)(Khi + row * KP + kc * 16 + t2);
                bh2[1] = *(const uint32_t*)(Khi + row * KP + kc * 16 + t2 + 8);
                bl2[0] = *(const uint32_t*)(Klo + row * KP + kc * 16 + t2);
                bl2[1] = *(const uint32_t*)(Klo + row * KP + kc * 16 + t2 + 8);
                mma16816(S[in], qhi[kc], bh2);
                mma16816(S[in], qhi[kc], bl2);
                mma16816(S[in], qlo[kc], bh2);
            }
        }

        // --- online softmax (rows g / g+8 of this warp's 16) ---
        float mx0 = -1e30f, mx1 = -1e30f;
#pragma unroll
        for (int in = 0; in < 16; in++) {
            S[in][0] *= 0.125f; S[in][1] *= 0.125f;
            S[in][2] *= 0.125f; S[in][3] *= 0.125f;
            mx0 = fmaxf(mx0, fmaxf(S[in][0], S[in][1]));
            mx1 = fmaxf(mx1, fmaxf(S[in][2], S[in][3]));
        }
        mx0 = fmaxf(mx0, __shfl_xor_sync(0xffffffffu, mx0, 1));
        mx0 = fmaxf(mx0, __shfl_xor_sync(0xffffffffu, mx0, 2));
        mx1 = fmaxf(mx1, __shfl_xor_sync(0xffffffffu, mx1, 1));
        mx1 = fmaxf(mx1, __shfl_xor_sync(0xffffffffu, mx1, 2));
        float nm0 = fmaxf(mrow0, mx0), nm1 = fmaxf(mrow1, mx1);
        float al0 = __expf(mrow0 - nm0), al1 = __expf(mrow1 - nm1);
        mrow0 = nm0; mrow1 = nm1;
        float sum0 = 0.f, sum1 = 0.f;
#pragma unroll
        for (int in = 0; in < 16; in++) {
            S[in][0] = __expf(S[in][0] - nm0);
            S[in][1] = __expf(S[in][1] - nm0);
            S[in][2] = __expf(S[in][2] - nm1);
            S[in][3] = __expf(S[in][3] - nm1);
            sum0 += S[in][0] + S[in][1];
            sum1 += S[in][2] + S[in][3];
        }
        sum0 += __shfl_xor_sync(0xffffffffu, sum0, 1);
        sum0 += __shfl_xor_sync(0xffffffffu, sum0, 2);
        sum1 += __shfl_xor_sync(0xffffffffu, sum1, 1);
        sum1 += __shfl_xor_sync(0xffffffffu, sum1, 2);
        lrow0 = lrow0 * al0 + sum0;
        lrow1 = lrow1 * al1 + sum1;
#pragma unroll
        for (int nt = 0; nt < 8; nt++) {
            O[nt][0] *= al0; O[nt][1] *= al0;
            O[nt][2] *= al1; O[nt][3] *= al1;
        }

        // --- O += P . V  (P packed from in-register S) ---
#pragma unroll
        for (int ks = 0; ks < 8; ks++) {
            uint32_t phi[4], plo[4];
            split2(make_float2(S[2 * ks][0],     S[2 * ks][1]),     phi[0], plo[0]);
            split2(make_float2(S[2 * ks][2],     S[2 * ks][3]),     phi[1], plo[1]);
            split2(make_float2(S[2 * ks + 1][0], S[2 * ks + 1][1]), phi[2], plo[2]);
            split2(make_float2(S[2 * ks + 1][2], S[2 * ks + 1][3]), phi[3], plo[3]);
#pragma unroll
            for (int nt = 0; nt < 8; nt++) {
                const int n = nt * 8 + g;
                uint32_t bh2[2], bl2[2];
                bh2[0] = *(const uint32_t*)(Vhi + n * VP + ks * 16 + t2);
                bh2[1] = *(const uint32_t*)(Vhi + n * VP + ks * 16 + t2 + 8);
                bl2[0] = *(const uint32_t*)(Vlo + n * VP + ks * 16 + t2);
                bl2[1] = *(const uint32_t*)(Vlo + n * VP + ks * 16 + t2 + 8);
                mma16816(O[nt], phi, bh2);
                mma16816(O[nt], phi, bl2);
                mma16816(O[nt], plo, bh2);
            }
        }
    }

    // --- epilogue: O /= l, write aT[b][t][h*64+c] ---
    const float inv0 = 1.f / lrow0, inv1 = 1.f / lrow1;
    const int r0 = t0 + warp * 16 + g;
    float* outB = aT + (size_t)b * 1024 * 512 + h * 64;
#pragma unroll
    for (int nt = 0; nt < 8; nt++) {
        const int c = nt * 8 + t2;
        *(float2*)(outB + (size_t)r0 * 512 + c) =
            make_float2(O[nt][0] * inv0, O[nt][1] * inv0);
        *(float2*)(outB + (size_t)(r0 + 8) * 512 + c) =
            make_float2(O[nt][2] * inv1, O[nt][3] * inv1);
    }
}

// ---------------------------------------------------------------------------
// GEMM core for QKV / proj (unchanged from R3)
// ---------------------------------------------------------------------------
template<int BM, int BN, int WM, int WN>
__device__ __forceinline__ void gemm_core(
    const float* __restrict__ Ag, int lda,
    const float* __restrict__ Bg, int ldb,
    int K, float* smem, float (*acc)[WN / 8][4])
{
    constexpr int BKP = 36;
    constexpr int MT = WM / 16, NT = WN / 8;
    constexpr int WARPS_N = BN / WN;
    float* As = smem;
    float* Bs = smem + BM * BKP;

    const int tid  = threadIdx.x;
    const int lane = tid & 31, warp = tid >> 5;
    const int wm = (warp / WARPS_N) * WM;
    const int wn = (warp % WARPS_N) * WN;
    const int g  = lane >> 2, t2 = (lane & 3) * 2;

    for (int k0 = 0; k0 < K; k0 += 32) {
#pragma unroll
        for (int i = tid; i < BM * 8; i += 256) {
            int r = i >> 3, c4 = (i & 7) * 4;
            *(float4*)&As[r * BKP + c4] = *(const float4*)(Ag + (size_t)r * lda + k0 + c4);
        }
#pragma unroll
        for (int i = tid; i < BN * 8; i += 256) {
            int r = i >> 3, c4 = (i & 7) * 4;
            *(float4*)&Bs[r * BKP + c4] = *(const float4*)(Bg + (size_t)r * ldb + k0 + c4);
        }
        __syncthreads();
#pragma unroll
        for (int kk = 0; kk < 32; kk += 16) {
            uint32_t ahi[MT][4], alo[MT][4], bhi[NT][2], blo[NT][2];
#pragma unroll
            for (int im = 0; im < MT; im++) {
                const float* r0 = &As[(wm + im * 16 + g) * BKP + kk + t2];
                const float* r1 = r0 + 8 * BKP;
                split2(*(const float2*)(r0),     ahi[im][0], alo[im][0]);
                split2(*(const float2*)(r1),     ahi[im][1], alo[im][1]);
                split2(*(const float2*)(r0 + 8), ahi[im][2], alo[im][2]);
                split2(*(const float2*)(r1 + 8), ahi[im][3], alo[im][3]);
            }
#pragma unroll
            for (int in = 0; in < NT; in++) {
                const float* c0 = &Bs[(wn + in * 8 + g) * BKP + kk + t2];
                split2(*(const float2*)(c0),     bhi[in][0], blo[in][0]);
                split2(*(const float2*)(c0 + 8), bhi[in][1], blo[in][1]);
            }
#pragma unroll
            for (int im = 0; im < MT; im++)
#pragma unroll
                for (int in = 0; in < NT; in++) {
                    mma16816(acc[im][in], ahi[im], bhi[in]);
                    mma16816(acc[im][in], ahi[im], blo[in]);
                    mma16816(acc[im][in], alo[im], bhi[in]);
                }
        }
        __syncthreads();
    }
}

// qkvT[b][l][o] = gnT[b][l][:] . W[o][:] + bias[o]
__global__ __launch_bounds__(256)
void qkv_mma(const float* __restrict__ gnT, const float* __restrict__ W,
             const float* __restrict__ bias, float* __restrict__ qkvT)
{
    __shared__ float smem[2 * 128 * 36];
    float acc[4][4][4] = {};
    const int m0 = blockIdx.x * 128, n0 = blockIdx.y * 128, b = blockIdx.z;
    gemm_core<128, 128, 64, 32>(gnT + ((size_t)b * 1024 + m0) * 512, 512,
                                W + (size_t)n0 * 512, 512, 512, smem, acc);
    const int lane = threadIdx.x & 31, warp = threadIdx.x >> 5;
    const int wm = (warp / 4) * 64, wn = (warp % 4) * 32;
    const int g = lane >> 2, t2 = (lane & 3) * 2;
    float* outB = qkvT + (size_t)b * 1024 * 1536;
#pragma unroll
    for (int in = 0; in < 4; in++) {
        const int c = n0 + wn + in * 8 + t2;
        const float bx = bias[c], by = bias[c + 1];
#pragma unroll
        for (int im = 0; im < 4; im++) {
            const int r = m0 + wm + im * 16 + g;
            *(float2*)(outB + (size_t)r * 1536 + c) =
                make_float2(acc[im][in][0] + bx, acc[im][in][1] + by);
            *(float2*)(outB + (size_t)(r + 8) * 1536 + c) =
                make_float2(acc[im][in][2] + bx, acc[im][in][3] + by);
        }
    }
}

// out[b][co][l] = x[b][co][l] + projW[co][:] . aT[b][l][:] + bias[co]
__global__ __launch_bounds__(256)
void proj_mma(const float* __restrict__ W, const float* __restrict__ aT,
              const float* __restrict__ bias, const float* __restrict__ x,
              float* __restrict__ out)
{
    __shared__ float smem[2 * 128 * 36];
    float acc[4][4][4] = {};
    const int m0 = blockIdx.x * 128, n0 = blockIdx.y * 128, b = blockIdx.z;
    gemm_core<128, 128, 64, 32>(W + (size_t)m0 * 512, 512,
                                aT + ((size_t)b * 1024 + n0) * 512, 512, 512, smem, acc);
    const int lane = threadIdx.x & 31, warp = threadIdx.x >> 5;
    const int wm = (warp / 4) * 64, wn = (warp % 4) * 32;
    const int g = lane >> 2, t2 = (lane & 3) * 2;
    const size_t bb = (size_t)b * 512 * 1024;
#pragma unroll
    for (int im = 0; im < 4; im++) {
        const int r = m0 + wm + im * 16 + g;
        const float bv0 = bias[r], bv1 = bias[r + 8];
#pragma unroll
        for (int in = 0; in < 4; in++) {
            const int c = n0 + wn + in * 8 + t2;
            size_t o0 = bb + (size_t)r * 1024 + c;
            size_t o1 = bb + (size_t)(r + 8) * 1024 + c;
            float2 x0 = *(const float2*)(x + o0);
            float2 x1 = *(const float2*)(x + o1);
            *(float2*)(out + o0) = make_float2(acc[im][in][0] + bv0 + x0.x,
                                               acc[im][in][1] + bv0 + x0.y);
            *(float2*)(out + o1) = make_float2(acc[im][in][2] + bv1 + x1.x,
                                               acc[im][in][3] + bv1 + x1.y);
        }
    }
}

// ---------------------------------------------------------------------------
// GroupNorm
// ---------------------------------------------------------------------------
__global__ void gn_kernel(const float* __restrict__ x, const float* __restrict__ w,
                          const float* __restrict__ bb, float* __restrict__ out)
{
    int b = blockIdx.x >> 5;
    int g = blockIdx.x & 31;
    const float4* xp = (const float4*)(x  + ((size_t)b * 512 + g * 16) * LQ);
    float4*       op = (float4*)      (out + ((size_t)b * 512 + g * 16) * LQ);
    int tid = threadIdx.x;

    float s = 0.f, ss = 0.f;
    float4 vals[16];
#pragma unroll
    for (int i = 0; i < 16; i++) {
        float4 v = xp[tid + i * 256];
        vals[i] = v;
        s  += v.x + v.y + v.z + v.w;
        ss += v.x * v.x + v.y * v.y + v.z * v.z + v.w * v.w;
    }
    __shared__ float rs[8], rss[8];
#pragma unroll
    for (int o = 16; o > 0; o >>= 1) {
        s  += __shfl_xor_sync(0xffffffffu, s, o);
        ss += __shfl_xor_sync(0xffffffffu, ss, o);
    }
    if ((tid & 31) == 0) { rs[tid >> 5] = s; rss[tid >> 5] = ss; }
    __syncthreads();
    float S = 0.f, SS = 0.f;
#pragma unroll
    for (int i = 0; i < 8; i++) { S += rs[i]; SS += rss[i]; }
    float mean = S * (1.f / 16384.f);
    float var  = SS * (1.f / 16384.f) - mean * mean;
    float inv  = rsqrtf(var + 1e-5f);
#pragma unroll
    for (int i = 0; i < 16; i++) {
        int idx = tid + i * 256;
        int c   = idx >> 8;
        float wc = w[g * 16 + c] * inv;
        float bc = bb[g * 16 + c] - mean * wc;
        float4 v = vals[i];
        v.x = v.x * wc + bc; v.y = v.y * wc + bc;
        v.z = v.z * wc + bc; v.w = v.w * wc + bc;
        op[idx] = v;
    }
}

// Generic fp32 transpose: dst[c][r] = src[r][c]
__global__ void transpose_kernel(const float* __restrict__ src, float* __restrict__ dst,
                                 int sld, int dld, size_t sstride, size_t dstride)
{
    __shared__ float t[32][33];
    const float* s = src + (size_t)blockIdx.z * sstride;
    float*       d = dst + (size_t)blockIdx.z * dstride;
    int r0 = blockIdx.y * 32, c0 = blockIdx.x * 32;
    int x = threadIdx.x, y = threadIdx.y;
#pragma unroll
    for (int k = 0; k < 32; k += 8)
        t[y + k][x] = s[(size_t)(r0 + y + k) * sld + c0 + x];
    __syncthreads();
#pragma unroll
    for (int k = 0; k < 32; k += 8)
        d[(size_t)(c0 + y + k) * dld + r0 + x] = t[x][y + k];
}

// ---------------------------------------------------------------------------
extern "C" void kernel_launch(void* const* d_in, const int* in_sizes, int n_in,
                              void* d_out, int out_size)
{
    const float* x      = (const float*)d_in[0];
    const float* gn_w   = (const float*)d_in[1];
    const float* gn_b   = (const float*)d_in[2];
    const float* qkv_w  = (const float*)d_in[3];
    const float* qkv_b  = (const float*)d_in[4];
    const float* proj_w = (const float*)d_in[5];
    const float* proj_b = (const float*)d_in[6];
    float* out = (float*)d_out;

    float *gn, *gnT, *qkvT, *aT;
    cudaGetSymbolAddress((void**)&gn,   g_gn);
    cudaGetSymbolAddress((void**)&gnT,  g_gnT);
    cudaGetSymbolAddress((void**)&qkvT, g_qkvT);
    cudaGetSymbolAddress((void**)&aT,   g_aT);

    const int FLASH_SMEM = (2 * 128 * 66 + 2 * 64 * 130) * 2;  // 67072 B
    cudaFuncSetAttribute(flash_kernel, cudaFuncAttributeMaxDynamicSharedMemorySize,
                         FLASH_SMEM);

    // 1. GroupNorm -> gn [b][c][l]
    gn_kernel<<<256, 256>>>(x, gn_w, gn_b, gn);
    // 2. gn -> gnT [b][l][c]
    transpose_kernel<<<dim3(32, 16, 8), dim3(32, 8)>>>(gn, gnT, 1024, 512,
                                                       (size_t)512 * 1024, (size_t)1024 * 512);
    // 3. qkvT[b][l][o] = gnT . W^T + bias
    qkv_mma<<<dim3(8, 12, 8), 256>>>(gnT, qkv_w, qkv_b, qkvT);
    // 4. fused attention -> aT[b][l][c]
    flash_kernel<<<dim3(8, 64), 256, FLASH_SMEM>>>(qkvT, aT);
    // 5. out = x + projW . aT^T + bias
    proj_mma<<<dim3(4, 8, 8), 256>>>(proj_w, aT, proj_b, x, out);
}

// round 6
// speedup vs baseline: 3.4577x; 1.7024x over previous
#include <cuda_runtime.h>
#include <cuda_bf16.h>
#include <cstdint>

#define LQ 1024
// B=8, C=512, heads=8/batch (bh=64), ch=64, groups=32

// ---------------------------------------------------------------------------
// Scratch
// ---------------------------------------------------------------------------
__device__ float g_gn  [(size_t)8 * 512  * 1024];    // [b][c][l]
__device__ float g_gnT [(size_t)8 * 1024 * 512];     // [b][l][c]
__device__ float g_qkvT[(size_t)8 * 1024 * 1536];    // [b][l][o]
__device__ float g_aT  [(size_t)8 * 1024 * 512];     // [b][l][c]

// ---------------------------------------------------------------------------
// helpers
// ---------------------------------------------------------------------------
__device__ __forceinline__ void split2(float2 f, uint32_t& hi, uint32_t& lo)
{
    __nv_bfloat162 h = __float22bfloat162_rn(f);
    float2 rem = make_float2(f.x - __bfloat162float(h.x),
                             f.y - __bfloat162float(h.y));
    __nv_bfloat162 l = __float22bfloat162_rn(rem);
    hi = *reinterpret_cast<uint32_t*>(&h);
    lo = *reinterpret_cast<uint32_t*>(&l);
}

// split float4 -> 4 bf16 hi + 4 bf16 lo, stored as 8B each
__device__ __forceinline__ void split_store4(__nv_bfloat16* ph, __nv_bfloat16* pl, float4 v)
{
    __nv_bfloat162 h0 = __float22bfloat162_rn(make_float2(v.x, v.y));
    __nv_bfloat162 h1 = __float22bfloat162_rn(make_float2(v.z, v.w));
    __nv_bfloat162 l0 = __float22bfloat162_rn(make_float2(v.x - __bfloat162float(h0.x),
                                                          v.y - __bfloat162float(h0.y)));
    __nv_bfloat162 l1 = __float22bfloat162_rn(make_float2(v.z - __bfloat162float(h1.x),
                                                          v.w - __bfloat162float(h1.y)));
    uint2 H, L;
    H.x = *reinterpret_cast<uint32_t*>(&h0); H.y = *reinterpret_cast<uint32_t*>(&h1);
    L.x = *reinterpret_cast<uint32_t*>(&l0); L.y = *reinterpret_cast<uint32_t*>(&l1);
    *reinterpret_cast<uint2*>(ph) = H;
    *reinterpret_cast<uint2*>(pl) = L;
}

__device__ __forceinline__ void mma16816(float* c, const uint32_t* a, const uint32_t* b)
{
    asm volatile(
        "mma.sync.aligned.m16n8k16.row.col.f32.bf16.bf16.f32 "
        "{%0,%1,%2,%3}, {%4,%5,%6,%7}, {%8,%9}, {%0,%1,%2,%3};"
        : "+f"(c[0]), "+f"(c[1]), "+f"(c[2]), "+f"(c[3])
        : "r"(a[0]), "r"(a[1]), "r"(a[2]), "r"(a[3]), "r"(b[0]), "r"(b[1]));
}

__device__ __forceinline__ uint32_t smem_u32(const void* p)
{
    uint32_t a;
    asm("{ .reg .u64 t; cvta.to.shared.u64 t, %1; cvt.u32.u64 %0, t; }" : "=r"(a) : "l"(p));
    return a;
}

__device__ __forceinline__ void ldsm_x4(uint32_t* r, uint32_t addr)
{
    asm volatile("ldmatrix.sync.aligned.m8n8.x4.shared.b16 {%0,%1,%2,%3}, [%4];"
                 : "=r"(r[0]), "=r"(r[1]), "=r"(r[2]), "=r"(r[3]) : "r"(addr));
}
__device__ __forceinline__ void ldsm_x4_t(uint32_t* r, uint32_t addr)
{
    asm volatile("ldmatrix.sync.aligned.m8n8.x4.trans.shared.b16 {%0,%1,%2,%3}, [%4];"
                 : "=r"(r[0]), "=r"(r[1]), "=r"(r[2]), "=r"(r[3]) : "r"(addr));
}

// ---------------------------------------------------------------------------
// Fused flash attention. 128 threads (4 warps), 2 CTAs/SM.
// CTA = one (bh, 128-row t-tile); warp owns 32 rows (2 m16-tiles).
// s-loop in 64-wide tiles. K,V stored [s][c] bf16 hi/lo, stride 72.
// K fragments via ldmatrix.x4 (hi+lo), V via ldmatrix.x4.trans.
// ---------------------------------------------------------------------------
__global__ __launch_bounds__(128, 2)
void flash_kernel(const float* __restrict__ qkvT, float* __restrict__ aT)
{
    constexpr int KP  = 72;          // bf16 row stride
    constexpr int TSZ = 64 * KP;     // bf16 units per buffer
    extern __shared__ __nv_bfloat16 sm[];
    __nv_bfloat16* Khi = sm;
    __nv_bfloat16* Klo = sm + TSZ;
    __nv_bfloat16* Vhi = sm + 2 * TSZ;
    __nv_bfloat16* Vlo = sm + 3 * TSZ;

    const int tid = threadIdx.x, lane = tid & 31, warp = tid >> 5;
    const int g = lane >> 2, t2 = (lane & 3) * 2;
    const int t0 = blockIdx.x * 128, bh = blockIdx.y;
    const int b = bh >> 3, h = bh & 7;
    const float* base = qkvT + (size_t)b * 1024 * 1536 + h * 192;

    // per-lane ldmatrix addresses (sel: 0,1 -> hi matrices, 2,3 -> lo)
    const uint32_t sb = smem_u32(sm);
    const int sel = lane >> 3;
    const uint32_t kbase = sb + (sel < 2 ? 0u : (uint32_t)TSZ * 2)
                         + ((lane & 7) * KP + (sel & 1) * 8) * 2;
    const uint32_t vbase = sb + (uint32_t)TSZ * 4 + (sel < 2 ? 0u : (uint32_t)TSZ * 2)
                         + (((sel & 1) * 8 + (lane & 7)) * KP) * 2;

    // --- Q fragments: 2 m-tiles, held in regs ---
    uint32_t qhi[2][4][4], qlo[2][4][4];
#pragma unroll
    for (int im = 0; im < 2; im++) {
        const int r0 = t0 + warp * 32 + im * 16 + g;
#pragma unroll
        for (int kc = 0; kc < 4; kc++) {
            const float* p0 = base + (size_t)r0 * 1536 + kc * 16 + t2;
            const float* p1 = p0 + 8 * 1536;
            split2(*(const float2*)p0,       qhi[im][kc][0], qlo[im][kc][0]);
            split2(*(const float2*)p1,       qhi[im][kc][1], qlo[im][kc][1]);
            split2(*(const float2*)(p0 + 8), qhi[im][kc][2], qlo[im][kc][2]);
            split2(*(const float2*)(p1 + 8), qhi[im][kc][3], qlo[im][kc][3]);
        }
    }

    float mrow[2][2], lrow[2][2];
#pragma unroll
    for (int im = 0; im < 2; im++) {
        mrow[im][0] = mrow[im][1] = -1e30f;
        lrow[im][0] = lrow[im][1] = 0.f;
    }
    float O[2][8][4] = {};

    for (int s0 = 0; s0 < LQ; s0 += 64) {
        if (s0) __syncthreads();
        // --- fill K,V tiles (64 rows x 64 cols each), bf16 hi/lo ---
#pragma unroll
        for (int j = 0; j < 8; j++) {
            int i = tid + j * 128;
            int r = i >> 4, c4 = (i & 15) * 4;
            const float* src = base + (size_t)(s0 + r) * 1536 + 64 + c4;
            float4 kv = *(const float4*)src;
            float4 vv = *(const float4*)(src + 64);
            split_store4(Khi + r * KP + c4, Klo + r * KP + c4, kv);
            split_store4(Vhi + r * KP + c4, Vlo + r * KP + c4, vv);
        }
        __syncthreads();

        // --- S = Q . K^T (2 m-tiles x 64 cols per warp) ---
        float S[2][8][4] = {};
#pragma unroll
        for (int kc = 0; kc < 4; kc++) {
#pragma unroll
            for (int in = 0; in < 8; in++) {
                uint32_t kb[4];
                ldsm_x4(kb, kbase + in * (8 * KP * 2) + kc * 32);
#pragma unroll
                for (int im = 0; im < 2; im++) {
                    mma16816(S[im][in], qhi[im][kc], kb);
                    mma16816(S[im][in], qhi[im][kc], kb + 2);
                    mma16816(S[im][in], qlo[im][kc], kb);
                }
            }
        }

        // --- online softmax ---
#pragma unroll
        for (int im = 0; im < 2; im++) {
            float mx0 = -1e30f, mx1 = -1e30f;
#pragma unroll
            for (int in = 0; in < 8; in++) {
                S[im][in][0] *= 0.125f; S[im][in][1] *= 0.125f;
                S[im][in][2] *= 0.125f; S[im][in][3] *= 0.125f;
                mx0 = fmaxf(mx0, fmaxf(S[im][in][0], S[im][in][1]));
                mx1 = fmaxf(mx1, fmaxf(S[im][in][2], S[im][in][3]));
            }
            mx0 = fmaxf(mx0, __shfl_xor_sync(0xffffffffu, mx0, 1));
            mx0 = fmaxf(mx0, __shfl_xor_sync(0xffffffffu, mx0, 2));
            mx1 = fmaxf(mx1, __shfl_xor_sync(0xffffffffu, mx1, 1));
            mx1 = fmaxf(mx1, __shfl_xor_sync(0xffffffffu, mx1, 2));
            float nm0 = fmaxf(mrow[im][0], mx0), nm1 = fmaxf(mrow[im][1], mx1);
            float al0 = __expf(mrow[im][0] - nm0), al1 = __expf(mrow[im][1] - nm1);
            mrow[im][0] = nm0; mrow[im][1] = nm1;
            float sa = 0.f, sb2 = 0.f;
#pragma unroll
            for (int in = 0; in < 8; in++) {
                S[im][in][0] = __expf(S[im][in][0] - nm0);
                S[im][in][1] = __expf(S[im][in][1] - nm0);
                S[im][in][2] = __expf(S[im][in][2] - nm1);
                S[im][in][3] = __expf(S[im][in][3] - nm1);
                sa  += S[im][in][0] + S[im][in][1];
                sb2 += S[im][in][2] + S[im][in][3];
            }
            sa  += __shfl_xor_sync(0xffffffffu, sa, 1);
            sa  += __shfl_xor_sync(0xffffffffu, sa, 2);
            sb2 += __shfl_xor_sync(0xffffffffu, sb2, 1);
            sb2 += __shfl_xor_sync(0xffffffffu, sb2, 2);
            lrow[im][0] = lrow[im][0] * al0 + sa;
            lrow[im][1] = lrow[im][1] * al1 + sb2;
#pragma unroll
            for (int nt = 0; nt < 8; nt++) {
                O[im][nt][0] *= al0; O[im][nt][1] *= al0;
                O[im][nt][2] *= al1; O[im][nt][3] *= al1;
            }
        }

        // --- O += P . V ---
#pragma unroll
        for (int ks = 0; ks < 4; ks++) {
            uint32_t phi[2][4], plo[2][4];
#pragma unroll
            for (int im = 0; im < 2; im++) {
                split2(make_float2(S[im][2*ks][0],   S[im][2*ks][1]),   phi[im][0], plo[im][0]);
                split2(make_float2(S[im][2*ks][2],   S[im][2*ks][3]),   phi[im][1], plo[im][1]);
                split2(make_float2(S[im][2*ks+1][0], S[im][2*ks+1][1]), phi[im][2], plo[im][2]);
                split2(make_float2(S[im][2*ks+1][2], S[im][2*ks+1][3]), phi[im][3], plo[im][3]);
            }
#pragma unroll
            for (int nt = 0; nt < 8; nt++) {
                uint32_t vb[4];
                ldsm_x4_t(vb, vbase + ks * (16 * KP * 2) + nt * 16);
#pragma unroll
                for (int im = 0; im < 2; im++) {
                    mma16816(O[im][nt], phi[im], vb);
                    mma16816(O[im][nt], phi[im], vb + 2);
                    mma16816(O[im][nt], plo[im], vb);
                }
            }
        }
    }

    // --- epilogue ---
    float* outB = aT + (size_t)b * 1024 * 512 + h * 64;
#pragma unroll
    for (int im = 0; im < 2; im++) {
        const float inv0 = 1.f / lrow[im][0], inv1 = 1.f / lrow[im][1];
        const int r0 = t0 + warp * 32 + im * 16 + g;
#pragma unroll
        for (int nt = 0; nt < 8; nt++) {
            const int c = nt * 8 + t2;
            *(float2*)(outB + (size_t)r0 * 512 + c) =
                make_float2(O[im][nt][0] * inv0, O[im][nt][1] * inv0);
            *(float2*)(outB + (size_t)(r0 + 8) * 512 + c) =
                make_float2(O[im][nt][2] * inv1, O[im][nt][3] * inv1);
        }
    }
}

// ---------------------------------------------------------------------------
// GEMM core: bf16 hi/lo pre-split at fill time, stride-40 smem (conflict-free)
// acc += A(BM x K, lda) . B(BN x K, ldb)^T, 3-product bf16. 256 threads.
// ---------------------------------------------------------------------------
template<int BM, int BN, int WM, int WN>
__device__ __forceinline__ void gemm_core(
    const float* __restrict__ Ag, int lda,
    const float* __restrict__ Bg, int ldb,
    int K, __nv_bfloat16* smem, float (*acc)[WN / 8][4])
{
    constexpr int ST = 40;
    constexpr int MT = WM / 16, NT = WN / 8;
    constexpr int WARPS_N = BN / WN;
    __nv_bfloat16* Ahi = smem;
    __nv_bfloat16* Alo = Ahi + BM * ST;
    __nv_bfloat16* Bhi = Alo + BM * ST;
    __nv_bfloat16* Blo = Bhi + BN * ST;

    const int tid  = threadIdx.x;
    const int lane = tid & 31, warp = tid >> 5;
    const int wm = (warp / WARPS_N) * WM;
    const int wn = (warp % WARPS_N) * WN;
    const int g  = lane >> 2, t2 = (lane & 3) * 2;

    for (int k0 = 0; k0 < K; k0 += 32) {
#pragma unroll
        for (int i = tid; i < BM * 8; i += 256) {
            int r = i >> 3, c4 = (i & 7) * 4;
            float4 v = *(const float4*)(Ag + (size_t)r * lda + k0 + c4);
            split_store4(Ahi + r * ST + c4, Alo + r * ST + c4, v);
        }
#pragma unroll
        for (int i = tid; i < BN * 8; i += 256) {
            int r = i >> 3, c4 = (i & 7) * 4;
            float4 v = *(const float4*)(Bg + (size_t)r * ldb + k0 + c4);
            split_store4(Bhi + r * ST + c4, Blo + r * ST + c4, v);
        }
        __syncthreads();
#pragma unroll
        for (int kk = 0; kk < 32; kk += 16) {
            uint32_t ahi[MT][4], alo[MT][4], bhi[NT][2], blo[NT][2];
#pragma unroll
            for (int im = 0; im < MT; im++) {
                const int off = (wm + im * 16 + g) * ST + kk + t2;
                ahi[im][0] = *(const uint32_t*)(Ahi + off);
                ahi[im][1] = *(const uint32_t*)(Ahi + off + 8 * ST);
                ahi[im][2] = *(const uint32_t*)(Ahi + off + 8);
                ahi[im][3] = *(const uint32_t*)(Ahi + off + 8 * ST + 8);
                alo[im][0] = *(const uint32_t*)(Alo + off);
                alo[im][1] = *(const uint32_t*)(Alo + off + 8 * ST);
                alo[im][2] = *(const uint32_t*)(Alo + off + 8);
                alo[im][3] = *(const uint32_t*)(Alo + off + 8 * ST + 8);
            }
#pragma unroll
            for (int in = 0; in < NT; in++) {
                const int off = (wn + in * 8 + g) * ST + kk + t2;
                bhi[in][0] = *(const uint32_t*)(Bhi + off);
                bhi[in][1] = *(const uint32_t*)(Bhi + off + 8);
                blo[in][0] = *(const uint32_t*)(Blo + off);
                blo[in][1] = *(const uint32_t*)(Blo + off + 8);
            }
#pragma unroll
            for (int im = 0; im < MT; im++)
#pragma unroll
                for (int in = 0; in < NT; in++) {
                    mma16816(acc[im][in], ahi[im], bhi[in]);
                    mma16816(acc[im][in], ahi[im], blo[in]);
                    mma16816(acc[im][in], alo[im], bhi[in]);
                }
        }
        __syncthreads();
    }
}

// qkvT[b][l][o] = gnT[b][l][:] . W[o][:] + bias[o]
__global__ __launch_bounds__(256)
void qkv_mma(const float* __restrict__ gnT, const float* __restrict__ W,
             const float* __restrict__ bias, float* __restrict__ qkvT)
{
    __shared__ __nv_bfloat16 smem[2 * (128 + 128) * 40];
    float acc[4][4][4] = {};
    const int m0 = blockIdx.x * 128, n0 = blockIdx.y * 128, b = blockIdx.z;
    gemm_core<128, 128, 64, 32>(gnT + ((size_t)b * 1024 + m0) * 512, 512,
                                W + (size_t)n0 * 512, 512, 512, smem, acc);
    const int lane = threadIdx.x & 31, warp = threadIdx.x >> 5;
    const int wm = (warp / 4) * 64, wn = (warp % 4) * 32;
    const int g = lane >> 2, t2 = (lane & 3) * 2;
    float* outB = qkvT + (size_t)b * 1024 * 1536;
#pragma unroll
    for (int in = 0; in < 4; in++) {
        const int c = n0 + wn + in * 8 + t2;
        const float bx = bias[c], by = bias[c + 1];
#pragma unroll
        for (int im = 0; im < 4; im++) {
            const int r = m0 + wm + im * 16 + g;
            *(float2*)(outB + (size_t)r * 1536 + c) =
                make_float2(acc[im][in][0] + bx, acc[im][in][1] + by);
            *(float2*)(outB + (size_t)(r + 8) * 1536 + c) =
                make_float2(acc[im][in][2] + bx, acc[im][in][3] + by);
        }
    }
}

// out[b][co][l] = x + projW[co][:] . aT[b][l][:] + bias[co]
__global__ __launch_bounds__(256)
void proj_mma(const float* __restrict__ W, const float* __restrict__ aT,
              const float* __restrict__ bias, const float* __restrict__ x,
              float* __restrict__ out)
{
    __shared__ __nv_bfloat16 smem[2 * (128 + 128) * 40];
    float acc[4][4][4] = {};
    const int m0 = blockIdx.x * 128, n0 = blockIdx.y * 128, b = blockIdx.z;
    gemm_core<128, 128, 64, 32>(W + (size_t)m0 * 512, 512,
                                aT + ((size_t)b * 1024 + n0) * 512, 512, 512, smem, acc);
    const int lane = threadIdx.x & 31, warp = threadIdx.x >> 5;
    const int wm = (warp / 4) * 64, wn = (warp % 4) * 32;
    const int g = lane >> 2, t2 = (lane & 3) * 2;
    const size_t bb = (size_t)b * 512 * 1024;
#pragma unroll
    for (int im = 0; im < 4; im++) {
        const int r = m0 + wm + im * 16 + g;
        const float bv0 = bias[r], bv1 = bias[r + 8];
#pragma unroll
        for (int in = 0; in < 4; in++) {
            const int c = n0 + wn + in * 8 + t2;
            size_t o0 = bb + (size_t)r * 1024 + c;
            size_t o1 = bb + (size_t)(r + 8) * 1024 + c;
            float2 x0 = *(const float2*)(x + o0);
            float2 x1 = *(const float2*)(x + o1);
            *(float2*)(out + o0) = make_float2(acc[im][in][0] + bv0 + x0.x,
                                               acc[im][in][1] + bv0 + x0.y);
            *(float2*)(out + o1) = make_float2(acc[im][in][2] + bv1 + x1.x,
                                               acc[im][in][3] + bv1 + x1.y);
        }
    }
}

// ---------------------------------------------------------------------------
// GroupNorm
// ---------------------------------------------------------------------------
__global__ void gn_kernel(const float* __restrict__ x, const float* __restrict__ w,
                          const float* __restrict__ bb, float* __restrict__ out)
{
    int b = blockIdx.x >> 5;
    int g = blockIdx.x & 31;
    const float4* xp = (const float4*)(x  + ((size_t)b * 512 + g * 16) * LQ);
    float4*       op = (float4*)      (out + ((size_t)b * 512 + g * 16) * LQ);
    int tid = threadIdx.x;

    float s = 0.f, ss = 0.f;
    float4 vals[16];
#pragma unroll
    for (int i = 0; i < 16; i++) {
        float4 v = xp[tid + i * 256];
        vals[i] = v;
        s  += v.x + v.y + v.z + v.w;
        ss += v.x * v.x + v.y * v.y + v.z * v.z + v.w * v.w;
    }
    __shared__ float rs[8], rss[8];
#pragma unroll
    for (int o = 16; o > 0; o >>= 1) {
        s  += __shfl_xor_sync(0xffffffffu, s, o);
        ss += __shfl_xor_sync(0xffffffffu, ss, o);
    }
    if ((tid & 31) == 0) { rs[tid >> 5] = s; rss[tid >> 5] = ss; }
    __syncthreads();
    float S = 0.f, SS = 0.f;
#pragma unroll
    for (int i = 0; i < 8; i++) { S += rs[i]; SS += rss[i]; }
    float mean = S * (1.f / 16384.f);
    float var  = SS * (1.f / 16384.f) - mean * mean;
    float inv  = rsqrtf(var + 1e-5f);
#pragma unroll
    for (int i = 0; i < 16; i++) {
        int idx = tid + i * 256;
        int c   = idx >> 8;
        float wc = w[g * 16 + c] * inv;
        float bc = bb[g * 16 + c] - mean * wc;
        float4 v = vals[i];
        v.x = v.x * wc + bc; v.y = v.y * wc + bc;
        v.z = v.z * wc + bc; v.w = v.w * wc + bc;
        op[idx] = v;
    }
}

// Generic fp32 transpose: dst[c][r] = src[r][c]
__global__ void transpose_kernel(const float* __restrict__ src, float* __restrict__ dst,
                                 int sld, int dld, size_t sstride, size_t dstride)
{
    __shared__ float t[32][33];
    const float* s = src + (size_t)blockIdx.z * sstride;
    float*       d = dst + (size_t)blockIdx.z * dstride;
    int r0 = blockIdx.y * 32, c0 = blockIdx.x * 32;
    int x = threadIdx.x, y = threadIdx.y;
#pragma unroll
    for (int k = 0; k < 32; k += 8)
        t[y + k][x] = s[(size_t)(r0 + y + k) * sld + c0 + x];
    __syncthreads();
#pragma unroll
    for (int k = 0; k < 32; k += 8)
        d[(size_t)(c0 + y + k) * dld + r0 + x] = t[x][y + k];
}

// ---------------------------------------------------------------------------
extern "C" void kernel_launch(void* const* d_in, const int* in_sizes, int n_in,
                              void* d_out, int out_size)
{
    const float* x      = (const float*)d_in[0];
    const float* gn_w   = (const float*)d_in[1];
    const float* gn_b   = (const float*)d_in[2];
    const float* qkv_w  = (const float*)d_in[3];
    const float* qkv_b  = (const float*)d_in[4];
    const float* proj_w = (const float*)d_in[5];
    const float* proj_b = (const float*)d_in[6];
    float* out = (float*)d_out;

    float *gn, *gnT, *qkvT, *aT;
    cudaGetSymbolAddress((void**)&gn,   g_gn);
    cudaGetSymbolAddress((void**)&gnT,  g_gnT);
    cudaGetSymbolAddress((void**)&qkvT, g_qkvT);
    cudaGetSymbolAddress((void**)&aT,   g_aT);

    const int FLASH_SMEM = 4 * 64 * 72 * 2;   // 36864 B
    cudaFuncSetAttribute(flash_kernel, cudaFuncAttributeMaxDynamicSharedMemorySize,
                         FLASH_SMEM);

    // 1. GroupNorm -> gn [b][c][l]
    gn_kernel<<<256, 256>>>(x, gn_w, gn_b, gn);
    // 2. gn -> gnT [b][l][c]
    transpose_kernel<<<dim3(32, 16, 8), dim3(32, 8)>>>(gn, gnT, 1024, 512,
                                                       (size_t)512 * 1024, (size_t)1024 * 512);
    // 3. qkvT[b][l][o] = gnT . W^T + bias
    qkv_mma<<<dim3(8, 12, 8), 256>>>(gnT, qkv_w, qkv_b, qkvT);
    // 4. fused attention -> aT[b][l][c]
    flash_kernel<<<dim3(8, 64), 128, FLASH_SMEM>>>(qkvT, aT);
    // 5. out = x + projW . aT^T + bias
    proj_mma<<<dim3(4, 8, 8), 256>>>(proj_w, aT, proj_b, x, out);
}

// round 8
// speedup vs baseline: 3.7452x; 1.0832x over previous
#include <cuda_runtime.h>
#include <cuda_bf16.h>
#include <cstdint>

#define LQ 1024
// B=8, C=512, heads=8/batch (bh=64), ch=64, groups=32

// ---------------------------------------------------------------------------
// Scratch (all GEMM operands pre-split bf16 hi/lo)
// ---------------------------------------------------------------------------
__device__ float2 g_stats[8 * 32];                        // (mean, inv) per (b,g)
__device__ __nv_bfloat16 g_gnT_hi[(size_t)8 * 1024 * 512];
__device__ __nv_bfloat16 g_gnT_lo[(size_t)8 * 1024 * 512];
__device__ __nv_bfloat16 g_wq_hi[1536 * 512];
__device__ __nv_bfloat16 g_wq_lo[1536 * 512];
__device__ __nv_bfloat16 g_wp_hi[512 * 512];
__device__ __nv_bfloat16 g_wp_lo[512 * 512];
__device__ __nv_bfloat16 g_qkv_hi[(size_t)8 * 1024 * 1536];  // [b][l][o], q pre-scaled by 1/8
__device__ __nv_bfloat16 g_qkv_lo[(size_t)8 * 1024 * 1536];
__device__ __nv_bfloat16 g_aT_hi[(size_t)8 * 1024 * 512];
__device__ __nv_bfloat16 g_aT_lo[(size_t)8 * 1024 * 512];

// ---------------------------------------------------------------------------
// helpers
// ---------------------------------------------------------------------------
__device__ __forceinline__ void split2(float2 f, uint32_t& hi, uint32_t& lo)
{
    __nv_bfloat162 h = __float22bfloat162_rn(f);
    float2 rem = make_float2(f.x - __bfloat162float(h.x),
                             f.y - __bfloat162float(h.y));
    __nv_bfloat162 l = __float22bfloat162_rn(rem);
    hi = *reinterpret_cast<uint32_t*>(&h);
    lo = *reinterpret_cast<uint32_t*>(&l);
}

__device__ __forceinline__ void mma16816(float* c, const uint32_t* a, const uint32_t* b)
{
    asm volatile(
        "mma.sync.aligned.m16n8k16.row.col.f32.bf16.bf16.f32 "
        "{%0,%1,%2,%3}, {%4,%5,%6,%7}, {%8,%9}, {%0,%1,%2,%3};"
        : "+f"(c[0]), "+f"(c[1]), "+f"(c[2]), "+f"(c[3])
        : "r"(a[0]), "r"(a[1]), "r"(a[2]), "r"(a[3]), "r"(b[0]), "r"(b[1]));
}

__device__ __forceinline__ uint32_t smem_u32(const void* p)
{
    uint32_t a;
    asm("{ .reg .u64 t; cvta.to.shared.u64 t, %1; cvt.u32.u64 %0, t; }" : "=r"(a) : "l"(p));
    return a;
}

__device__ __forceinline__ void ldsm_x4(uint32_t* r, uint32_t addr)
{
    asm volatile("ldmatrix.sync.aligned.m8n8.x4.shared.b16 {%0,%1,%2,%3}, [%4];"
                 : "=r"(r[0]), "=r"(r[1]), "=r"(r[2]), "=r"(r[3]) : "r"(addr));
}
__device__ __forceinline__ void ldsm_x4_t(uint32_t* r, uint32_t addr)
{
    asm volatile("ldmatrix.sync.aligned.m8n8.x4.trans.shared.b16 {%0,%1,%2,%3}, [%4];"
                 : "=r"(r[0]), "=r"(r[1]), "=r"(r[2]), "=r"(r[3]) : "r"(addr));
}

// ---------------------------------------------------------------------------
// GN pass 1: per-(b,group) mean / inv-std
// ---------------------------------------------------------------------------
__global__ void gn_stats(const float* __restrict__ x, float2* __restrict__ stats)
{
    int b = blockIdx.x >> 5, g = blockIdx.x & 31;
    const float4* xp = (const float4*)(x + ((size_t)b * 512 + g * 16) * LQ);
    int tid = threadIdx.x;
    float s = 0.f, ss = 0.f;
    for (int i = tid; i < 4096; i += 256) {
        float4 v = xp[i];
        s  += v.x + v.y + v.z + v.w;
        ss += v.x * v.x + v.y * v.y + v.z * v.z + v.w * v.w;
    }
    __shared__ float rs[8], rss[8];
#pragma unroll
    for (int o = 16; o > 0; o >>= 1) {
        s  += __shfl_xor_sync(0xffffffffu, s, o);
        ss += __shfl_xor_sync(0xffffffffu, ss, o);
    }
    if ((tid & 31) == 0) { rs[tid >> 5] = s; rss[tid >> 5] = ss; }
    __syncthreads();
    if (tid == 0) {
        float S = 0.f, SS = 0.f;
#pragma unroll
        for (int i = 0; i < 8; i++) { S += rs[i]; SS += rss[i]; }
        float mean = S * (1.f / 16384.f);
        float var  = SS * (1.f / 16384.f) - mean * mean;
        stats[blockIdx.x] = make_float2(mean, rsqrtf(var + 1e-5f));
    }
}

// GN pass 2: normalize + transpose + split -> gnT hi/lo [b][l][c]
__global__ void gn_tsplit(const float* __restrict__ x, const float2* __restrict__ stats,
                          const float* __restrict__ w, const float* __restrict__ bb,
                          __nv_bfloat16* __restrict__ dhi, __nv_bfloat16* __restrict__ dlo)
{
    __shared__ float t[32][33];
    const int b = blockIdx.z;
    const int c0 = blockIdx.y * 32, l0 = blockIdx.x * 32;
    const int tx = threadIdx.x, ty = threadIdx.y;
#pragma unroll
    for (int k = 0; k < 32; k += 8)
        t[ty + k][tx] = x[((size_t)b * 512 + c0 + ty + k) * LQ + l0 + tx];
    __syncthreads();
    const int c = c0 + tx;
    float2 st = stats[b * 32 + (c >> 4)];
    const float wc = w[c] * st.y;
    const float bc = bb[c] - st.x * wc;
#pragma unroll
    for (int k = 0; k < 32; k += 8) {
        float v = t[tx][ty + k] * wc + bc;
        __nv_bfloat16 h = __float2bfloat16(v);
        __nv_bfloat16 l = __float2bfloat16(v - __bfloat162float(h));
        size_t o = ((size_t)b * 1024 + l0 + ty + k) * 512 + c;
        dhi[o] = h;
        dlo[o] = l;
    }
}

// Weight split (n elements, multiple of 1024; 1 float4 per thread)
__global__ void wsplit_kernel(const float* __restrict__ w,
                              __nv_bfloat16* __restrict__ hi, __nv_bfloat16* __restrict__ lo)
{
    int i = blockIdx.x * 256 + threadIdx.x;
    float4 v = ((const float4*)w)[i];
    uint32_t h0, l0, h1, l1;
    split2(make_float2(v.x, v.y), h0, l0);
    split2(make_float2(v.z, v.w), h1, l1);
    ((uint2*)hi)[i] = make_uint2(h0, h1);
    ((uint2*)lo)[i] = make_uint2(l0, l1);
}

// ---------------------------------------------------------------------------
// GEMM core, pre-split operands: acc += A(BM x K).B(BN x K)^T, 3-product.
// Fill = pure 16B copies. 256 threads. Stride 40 (conflict-free frag loads).
// ---------------------------------------------------------------------------
template<int BM, int BN, int WM, int WN>
__device__ __forceinline__ void gemm_core(
    const __nv_bfloat16* __restrict__ Agh, const __nv_bfloat16* __restrict__ Agl, int lda,
    const __nv_bfloat16* __restrict__ Bgh, const __nv_bfloat16* __restrict__ Bgl, int ldb,
    int K, __nv_bfloat16* smem, float (*acc)[WN / 8][4])
{
    constexpr int ST = 40;
    constexpr int MT = WM / 16, NT = WN / 8;
    constexpr int WARPS_N = BN / WN;
    __nv_bfloat16* Ahi = smem;
    __nv_bfloat16* Alo = Ahi + BM * ST;
    __nv_bfloat16* Bhi = Alo + BM * ST;
    __nv_bfloat16* Blo = Bhi + BN * ST;

    const int tid  = threadIdx.x;
    const int lane = tid & 31, warp = tid >> 5;
    const int wm = (warp / WARPS_N) * WM;
    const int wn = (warp % WARPS_N) * WN;
    const int g  = lane >> 2, t2 = (lane & 3) * 2;

    for (int k0 = 0; k0 < K; k0 += 32) {
#pragma unroll
        for (int i = tid; i < BM * 4; i += 256) {
            int r = i >> 2, s = (i & 3) * 8;
            *(uint4*)(Ahi + r * ST + s) = *(const uint4*)(Agh + (size_t)r * lda + k0 + s);
            *(uint4*)(Alo + r * ST + s) = *(const uint4*)(Agl + (size_t)r * lda + k0 + s);
        }
#pragma unroll
        for (int i = tid; i < BN * 4; i += 256) {
            int r = i >> 2, s = (i & 3) * 8;
            *(uint4*)(Bhi + r * ST + s) = *(const uint4*)(Bgh + (size_t)r * ldb + k0 + s);
            *(uint4*)(Blo + r * ST + s) = *(const uint4*)(Bgl + (size_t)r * ldb + k0 + s);
        }
        __syncthreads();
#pragma unroll
        for (int kk = 0; kk < 32; kk += 16) {
            uint32_t ahi[MT][4], alo[MT][4], bhi[NT][2], blo[NT][2];
#pragma unroll
            for (int im = 0; im < MT; im++) {
                const int off = (wm + im * 16 + g) * ST + kk + t2;
                ahi[im][0] = *(const uint32_t*)(Ahi + off);
                ahi[im][1] = *(const uint32_t*)(Ahi + off + 8 * ST);
                ahi[im][2] = *(const uint32_t*)(Ahi + off + 8);
                ahi[im][3] = *(const uint32_t*)(Ahi + off + 8 * ST + 8);
                alo[im][0] = *(const uint32_t*)(Alo + off);
                alo[im][1] = *(const uint32_t*)(Alo + off + 8 * ST);
                alo[im][2] = *(const uint32_t*)(Alo + off + 8);
                alo[im][3] = *(const uint32_t*)(Alo + off + 8 * ST + 8);
            }
#pragma unroll
            for (int in = 0; in < NT; in++) {
                const int off = (wn + in * 8 + g) * ST + kk + t2;
                bhi[in][0] = *(const uint32_t*)(Bhi + off);
                bhi[in][1] = *(const uint32_t*)(Bhi + off + 8);
                blo[in][0] = *(const uint32_t*)(Blo + off);
                blo[in][1] = *(const uint32_t*)(Blo + off + 8);
            }
#pragma unroll
            for (int im = 0; im < MT; im++)
#pragma unroll
                for (int in = 0; in < NT; in++) {
                    mma16816(acc[im][in], ahi[im], bhi[in]);
                    mma16816(acc[im][in], ahi[im], blo[in]);
                    mma16816(acc[im][in], alo[im], bhi[in]);
                }
        }
        __syncthreads();
    }
}

// qkv: [b][l][o] = gnT . W^T + bias, output split bf16, q cols pre-scaled 1/8
__global__ __launch_bounds__(256)
void qkv_mma(const __nv_bfloat16* __restrict__ gh, const __nv_bfloat16* __restrict__ gl,
             const __nv_bfloat16* __restrict__ wh, const __nv_bfloat16* __restrict__ wl,
             const float* __restrict__ bias,
             __nv_bfloat16* __restrict__ qh, __nv_bfloat16* __restrict__ ql)
{
    __shared__ __nv_bfloat16 smem[2 * (128 + 128) * 40];
    float acc[4][4][4] = {};
    const int m0 = blockIdx.x * 128, n0 = blockIdx.y * 128, b = blockIdx.z;
    gemm_core<128, 128, 64, 32>(gh + ((size_t)b * 1024 + m0) * 512,
                                gl + ((size_t)b * 1024 + m0) * 512, 512,
                                wh + (size_t)n0 * 512, wl + (size_t)n0 * 512, 512,
                                512, smem, acc);
    const int lane = threadIdx.x & 31, warp = threadIdx.x >> 5;
    const int wm = (warp / 4) * 64, wn = (warp % 4) * 32;
    const int g = lane >> 2, t2 = (lane & 3) * 2;
#pragma unroll
    for (int in = 0; in < 4; in++) {
        const int c = n0 + wn + in * 8 + t2;
        const float sc = ((c % 192) < 64) ? 0.125f : 1.f;
        const float bx = bias[c] * sc, by = bias[c + 1] * sc;
#pragma unroll
        for (int im = 0; im < 4; im++) {
            const int r = m0 + wm + im * 16 + g;
            size_t o0 = ((size_t)b * 1024 + r) * 1536 + c;
            size_t o1 = o0 + 8 * 1536;
            uint32_t h, l;
            split2(make_float2(acc[im][in][0] * sc + bx, acc[im][in][1] * sc + by), h, l);
            *(uint32_t*)(qh + o0) = h; *(uint32_t*)(ql + o0) = l;
            split2(make_float2(acc[im][in][2] * sc + bx, acc[im][in][3] * sc + by), h, l);
            *(uint32_t*)(qh + o1) = h; *(uint32_t*)(ql + o1) = l;
        }
    }
}

// out[b][co][l] = x + projW . aT^T + bias
__global__ __launch_bounds__(256)
void proj_mma(const __nv_bfloat16* __restrict__ wh, const __nv_bfloat16* __restrict__ wl,
              const __nv_bfloat16* __restrict__ ah, const __nv_bfloat16* __restrict__ al,
              const float* __restrict__ bias, const float* __restrict__ x,
              float* __restrict__ out)
{
    __shared__ __nv_bfloat16 smem[2 * (128 + 128) * 40];
    float acc[4][4][4] = {};
    const int m0 = blockIdx.x * 128, n0 = blockIdx.y * 128, b = blockIdx.z;
    gemm_core<128, 128, 64, 32>(wh + (size_t)m0 * 512, wl + (size_t)m0 * 512, 512,
                                ah + ((size_t)b * 1024 + n0) * 512,
                                al + ((size_t)b * 1024 + n0) * 512, 512,
                                512, smem, acc);
    const int lane = threadIdx.x & 31, warp = threadIdx.x >> 5;
    const int wm = (warp / 4) * 64, wn = (warp % 4) * 32;
    const int g = lane >> 2, t2 = (lane & 3) * 2;
    const size_t bb = (size_t)b * 512 * 1024;
#pragma unroll
    for (int im = 0; im < 4; im++) {
        const int r = m0 + wm + im * 16 + g;
        const float bv0 = bias[r], bv1 = bias[r + 8];
#pragma unroll
        for (int in = 0; in < 4; in++) {
            const int c = n0 + wn + in * 8 + t2;
            size_t o0 = bb + (size_t)r * 1024 + c;
            size_t o1 = bb + (size_t)(r + 8) * 1024 + c;
            float2 x0 = *(const float2*)(x + o0);
            float2 x1 = *(const float2*)(x + o1);
            *(float2*)(out + o0) = make_float2(acc[im][in][0] + bv0 + x0.x,
                                               acc[im][in][1] + bv0 + x0.y);
            *(float2*)(out + o1) = make_float2(acc[im][in][2] + bv1 + x1.x,
                                               acc[im][in][3] + bv1 + x1.y);
        }
    }
}

// ---------------------------------------------------------------------------
// Fused flash attention, pre-split inputs. 128 threads, 2 CTAs/SM.
// Q tile (128x64) in smem hi/lo; K/V tiles 64x64 hi/lo; all fills = copies.
// ---------------------------------------------------------------------------
__global__ __launch_bounds__(128, 2)
void flash_kernel(const __nv_bfloat16* __restrict__ qkh,
                  const __nv_bfloat16* __restrict__ qkl,
                  __nv_bfloat16* __restrict__ aTh, __nv_bfloat16* __restrict__ aTl)
{
    constexpr int KP  = 72;
    constexpr int QSZ = 128 * KP;
    constexpr int TSZ = 64 * KP;
    extern __shared__ __nv_bfloat16 sm[];
    __nv_bfloat16* Qhi = sm;
    __nv_bfloat16* Qlo = sm + QSZ;
    __nv_bfloat16* Khi = sm + 2 * QSZ;
    __nv_bfloat16* Klo = Khi + TSZ;
    __nv_bfloat16* Vhi = Klo + TSZ;
    __nv_bfloat16* Vlo = Vhi + TSZ;

    const int tid = threadIdx.x, lane = tid & 31, warp = tid >> 5;
    const int g = lane >> 2, t2 = (lane & 3) * 2;
    const int t0 = blockIdx.x * 128, bh = blockIdx.y;
    const int b = bh >> 3, h = bh & 7;
    const __nv_bfloat16* bh_hi = qkh + (size_t)b * 1024 * 1536 + h * 192;
    const __nv_bfloat16* bh_lo = qkl + (size_t)b * 1024 * 1536 + h * 192;

    const uint32_t sb = smem_u32(sm);
    const int sel = lane >> 3;
    // B-fragment ldmatrix bases: matrices 0,1 from hi buffer, 2,3 from lo.
    const uint32_t kbase = sb + 4 * QSZ + (sel < 2 ? 0u : 2u * TSZ)
                         + ((lane & 7) * KP + (sel & 1) * 8) * 2;
    const uint32_t vbase = sb + 4 * QSZ + 4 * TSZ + (sel < 2 ? 0u : 2u * TSZ)
                         + (((sel & 1) * 8 + (lane & 7)) * KP) * 2;
    // Q (A-fragment) ldmatrix base for this warp
    const uint32_t qbase = sb + ((warp * 32 + (lane & 15)) * KP + (lane >> 4) * 8) * 2;

    // --- fill Q tile once (copy) ---
#pragma unroll
    for (int j = 0; j < 8; j++) {
        int i = tid + j * 128;            // 0..1023
        int r = i >> 3, s = (i & 7) * 8;
        const size_t src = (size_t)(t0 + r) * 1536 + s;
        *(uint4*)(Qhi + r * KP + s) = *(const uint4*)(bh_hi + src);
        *(uint4*)(Qlo + r * KP + s) = *(const uint4*)(bh_lo + src);
    }

    float mrow[2][2], lrow[2][2];
#pragma unroll
    for (int im = 0; im < 2; im++) {
        mrow[im][0] = mrow[im][1] = -1e30f;
        lrow[im][0] = lrow[im][1] = 0.f;
    }
    float O[2][8][4] = {};

    for (int s0 = 0; s0 < LQ; s0 += 64) {
        if (s0) __syncthreads();
        // --- fill K,V tiles (copies) ---
#pragma unroll
        for (int j = 0; j < 4; j++) {
            int i = tid + j * 128;        // 0..511
            int r = i >> 3, s = (i & 7) * 8;
            const size_t src = (size_t)(s0 + r) * 1536 + 64 + s;
            *(uint4*)(Khi + r * KP + s) = *(const uint4*)(bh_hi + src);
            *(uint4*)(Klo + r * KP + s) = *(const uint4*)(bh_lo + src);
            *(uint4*)(Vhi + r * KP + s) = *(const uint4*)(bh_hi + src + 64);
            *(uint4*)(Vlo + r * KP + s) = *(const uint4*)(bh_lo + src + 64);
        }
        __syncthreads();

        // --- S = Q . K^T ---
        float S[2][8][4] = {};
#pragma unroll
        for (int kc = 0; kc < 4; kc++) {
            uint32_t qhf[2][4], qlf[2][4];
#pragma unroll
            for (int im = 0; im < 2; im++) {
                uint32_t a = qbase + im * (16 * KP * 2) + kc * 32;
                ldsm_x4(qhf[im], a);
                ldsm_x4(qlf[im], a + QSZ * 2);
            }
#pragma unroll
            for (int in = 0; in < 8; in++) {
                uint32_t kb[4];
                ldsm_x4(kb, kbase + in * (8 * KP * 2) + kc * 32);
#pragma unroll
                for (int im = 0; im < 2; im++) {
                    mma16816(S[im][in], qhf[im], kb);
                    mma16816(S[im][in], qhf[im], kb + 2);
                    mma16816(S[im][in], qlf[im], kb);
                }
            }
        }

        // --- online softmax (scale already folded into q) ---
#pragma unroll
        for (int im = 0; im < 2; im++) {
            float mx0 = -1e30f, mx1 = -1e30f;
#pragma unroll
            for (int in = 0; in < 8; in++) {
                mx0 = fmaxf(mx0, fmaxf(S[im][in][0], S[im][in][1]));
                mx1 = fmaxf(mx1, fmaxf(S[im][in][2], S[im][in][3]));
            }
            mx0 = fmaxf(mx0, __shfl_xor_sync(0xffffffffu, mx0, 1));
            mx0 = fmaxf(mx0, __shfl_xor_sync(0xffffffffu, mx0, 2));
            mx1 = fmaxf(mx1, __shfl_xor_sync(0xffffffffu, mx1, 1));
            mx1 = fmaxf(mx1, __shfl_xor_sync(0xffffffffu, mx1, 2));
            float nm0 = fmaxf(mrow[im][0], mx0), nm1 = fmaxf(mrow[im][1], mx1);
            float al0 = __expf(mrow[im][0] - nm0), al1 = __expf(mrow[im][1] - nm1);
            mrow[im][0] = nm0; mrow[im][1] = nm1;
            float sa = 0.f, sb2 = 0.f;
#pragma unroll
            for (int in = 0; in < 8; in++) {
                S[im][in][0] = __expf(S[im][in][0] - nm0);
                S[im][in][1] = __expf(S[im][in][1] - nm0);
                S[im][in][2] = __expf(S[im][in][2] - nm1);
                S[im][in][3] = __expf(S[im][in][3] - nm1);
                sa  += S[im][in][0] + S[im][in][1];
                sb2 += S[im][in][2] + S[im][in][3];
            }
            sa  += __shfl_xor_sync(0xffffffffu, sa, 1);
            sa  += __shfl_xor_sync(0xffffffffu, sa, 2);
            sb2 += __shfl_xor_sync(0xffffffffu, sb2, 1);
            sb2 += __shfl_xor_sync(0xffffffffu, sb2, 2);
            lrow[im][0] = lrow[im][0] * al0 + sa;
            lrow[im][1] = lrow[im][1] * al1 + sb2;
#pragma unroll
            for (int nt = 0; nt < 8; nt++) {
                O[im][nt][0] *= al0; O[im][nt][1] *= al0;
                O[im][nt][2] *= al1; O[im][nt][3] *= al1;
            }
        }

        // --- O += P . V ---
#pragma unroll
        for (int ks = 0; ks < 4; ks++) {
            uint32_t phi[2][4], plo[2][4];
#pragma unroll
            for (int im = 0; im < 2; im++) {
                split2(make_float2(S[im][2*ks][0],   S[im][2*ks][1]),   phi[im][0], plo[im][0]);
                split2(make_float2(S[im][2*ks][2],   S[im][2*ks][3]),   phi[im][1], plo[im][1]);
                split2(make_float2(S[im][2*ks+1][0], S[im][2*ks+1][1]), phi[im][2], plo[im][2]);
                split2(make_float2(S[im][2*ks+1][2], S[im][2*ks+1][3]), phi[im][3], plo[im][3]);
            }
#pragma unroll
            for (int nt = 0; nt < 8; nt++) {
                uint32_t vb[4];
                ldsm_x4_t(vb, vbase + ks * (16 * KP * 2) + nt * 16);
#pragma unroll
                for (int im = 0; im < 2; im++) {
                    mma16816(O[im][nt], phi[im], vb);
                    mma16816(O[im][nt], phi[im], vb + 2);
                    mma16816(O[im][nt], plo[im], vb);
                }
            }
        }
    }

    // --- epilogue: write aT hi/lo ---
    __nv_bfloat16* oh = aTh + (size_t)b * 1024 * 512 + h * 64;
    __nv_bfloat16* ol = aTl + (size_t)b * 1024 * 512 + h * 64;
#pragma unroll
    for (int im = 0; im < 2; im++) {
        const float inv0 = 1.f / lrow[im][0], inv1 = 1.f / lrow[im][1];
        const int r0 = t0 + warp * 32 + im * 16 + g;
#pragma unroll
        for (int nt = 0; nt < 8; nt++) {
            const int c = nt * 8 + t2;
            size_t o0 = (size_t)r0 * 512 + c;
            size_t o1 = o0 + 8 * 512;
            uint32_t hh, ll;
            split2(make_float2(O[im][nt][0] * inv0, O[im][nt][1] * inv0), hh, ll);
            *(uint32_t*)(oh + o0) = hh; *(uint32_t*)(ol + o0) = ll;
            split2(make_float2(O[im][nt][2] * inv1, O[im][nt][3] * inv1), hh, ll);
            *(uint32_t*)(oh + o1) = hh; *(uint32_t*)(ol + o1) = ll;
        }
    }
}

// ---------------------------------------------------------------------------
extern "C" void kernel_launch(void* const* d_in, const int* in_sizes, int n_in,
                              void* d_out, int out_size)
{
    const float* x      = (const float*)d_in[0];
    const float* gn_w   = (const float*)d_in[1];
    const float* gn_b   = (const float*)d_in[2];
    const float* qkv_w  = (const float*)d_in[3];
    const float* qkv_b  = (const float*)d_in[4];
    const float* proj_w = (const float*)d_in[5];
    const float* proj_b = (const float*)d_in[6];
    float* out = (float*)d_out;

    float2* stats;
    __nv_bfloat16 *gh, *gl, *wqh, *wql, *wph, *wpl, *qh, *ql, *ah, *al;
    cudaGetSymbolAddress((void**)&stats, g_stats);
    cudaGetSymbolAddress((void**)&gh,  g_gnT_hi);
    cudaGetSymbolAddress((void**)&gl,  g_gnT_lo);
    cudaGetSymbolAddress((void**)&wqh, g_wq_hi);
    cudaGetSymbolAddress((void**)&wql, g_wq_lo);
    cudaGetSymbolAddress((void**)&wph, g_wp_hi);
    cudaGetSymbolAddress((void**)&wpl, g_wp_lo);
    cudaGetSymbolAddress((void**)&qh,  g_qkv_hi);
    cudaGetSymbolAddress((void**)&ql,  g_qkv_lo);
    cudaGetSymbolAddress((void**)&ah,  g_aT_hi);
    cudaGetSymbolAddress((void**)&al,  g_aT_lo);

    const int FLASH_SMEM = (2 * 128 * 72 + 4 * 64 * 72) * 2;  // 73728 B
    cudaFuncSetAttribute(flash_kernel, cudaFuncAttributeMaxDynamicSharedMemorySize,
                         FLASH_SMEM);

    // weights -> bf16 hi/lo (once per call, small)
    wsplit_kernel<<<768, 256>>>(qkv_w, wqh, wql);
    wsplit_kernel<<<256, 256>>>(proj_w, wph, wpl);
    // GroupNorm stats, then fused normalize+transpose+split
    gn_stats<<<256, 256>>>(x, stats);
    gn_tsplit<<<dim3(32, 16, 8), dim3(32, 8)>>>(x, stats, gn_w, gn_b, gh, gl);
    // qkv (q pre-scaled by 1/8), pre-split output
    qkv_mma<<<dim3(8, 12, 8), 256>>>(gh, gl, wqh, wql, qkv_b, qh, ql);
    // fused attention -> aT hi/lo
    flash_kernel<<<dim3(8, 64), 128, FLASH_SMEM>>>(qh, ql, ah, al);
    // out = x + projW . aT^T + bias
    proj_mma<<<dim3(4, 8, 8), 256>>>(wph, wpl, ah, al, proj_b, x, out);
}

// round 9
// speedup vs baseline: 4.1042x; 1.0958x over previous
#include <cuda_runtime.h>
#include <cuda_bf16.h>
#include <cstdint>

#define LQ 1024
// B=8, C=512, heads=8/batch (bh=64), ch=64, groups=32

// ---------------------------------------------------------------------------
// Scratch (all GEMM operands pre-split bf16 hi/lo)
// ---------------------------------------------------------------------------
__device__ float2 g_stats[8 * 32];
__device__ __nv_bfloat16 g_gnT_hi[(size_t)8 * 1024 * 512];
__device__ __nv_bfloat16 g_gnT_lo[(size_t)8 * 1024 * 512];
__device__ __nv_bfloat16 g_wq_hi[1536 * 512];
__device__ __nv_bfloat16 g_wq_lo[1536 * 512];
__device__ __nv_bfloat16 g_wp_hi[512 * 512];
__device__ __nv_bfloat16 g_wp_lo[512 * 512];
__device__ __nv_bfloat16 g_qkv_hi[(size_t)8 * 1024 * 1536];  // q pre-scaled 1/8
__device__ __nv_bfloat16 g_qkv_lo[(size_t)8 * 1024 * 1536];
__device__ __nv_bfloat16 g_aT_hi[(size_t)8 * 1024 * 512];
__device__ __nv_bfloat16 g_aT_lo[(size_t)8 * 1024 * 512];

// ---------------------------------------------------------------------------
// helpers
// ---------------------------------------------------------------------------
__device__ __forceinline__ void split2(float2 f, uint32_t& hi, uint32_t& lo)
{
    __nv_bfloat162 h = __float22bfloat162_rn(f);
    float2 rem = make_float2(f.x - __bfloat162float(h.x),
                             f.y - __bfloat162float(h.y));
    __nv_bfloat162 l = __float22bfloat162_rn(rem);
    hi = *reinterpret_cast<uint32_t*>(&h);
    lo = *reinterpret_cast<uint32_t*>(&l);
}

__device__ __forceinline__ void mma16816(float* c, const uint32_t* a, const uint32_t* b)
{
    asm volatile(
        "mma.sync.aligned.m16n8k16.row.col.f32.bf16.bf16.f32 "
        "{%0,%1,%2,%3}, {%4,%5,%6,%7}, {%8,%9}, {%0,%1,%2,%3};"
        : "+f"(c[0]), "+f"(c[1]), "+f"(c[2]), "+f"(c[3])
        : "r"(a[0]), "r"(a[1]), "r"(a[2]), "r"(a[3]), "r"(b[0]), "r"(b[1]));
}

__device__ __forceinline__ uint32_t smem_u32(const void* p)
{
    uint32_t a;
    asm("{ .reg .u64 t; cvta.to.shared.u64 t, %1; cvt.u32.u64 %0, t; }" : "=r"(a) : "l"(p));
    return a;
}

__device__ __forceinline__ void ldsm_x4(uint32_t* r, uint32_t addr)
{
    asm volatile("ldmatrix.sync.aligned.m8n8.x4.shared.b16 {%0,%1,%2,%3}, [%4];"
                 : "=r"(r[0]), "=r"(r[1]), "=r"(r[2]), "=r"(r[3]) : "r"(addr));
}
__device__ __forceinline__ void ldsm_x4_t(uint32_t* r, uint32_t addr)
{
    asm volatile("ldmatrix.sync.aligned.m8n8.x4.trans.shared.b16 {%0,%1,%2,%3}, [%4];"
                 : "=r"(r[0]), "=r"(r[1]), "=r"(r[2]), "=r"(r[3]) : "r"(addr));
}

__device__ __forceinline__ void cp16(uint32_t dst, const void* src)
{
    asm volatile("cp.async.cg.shared.global [%0], [%1], 16;" :: "r"(dst), "l"(src));
}
#define CP_COMMIT() asm volatile("cp.async.commit_group;" ::: "memory")
#define CP_WAIT1()  asm volatile("cp.async.wait_group 1;" ::: "memory")

// ---------------------------------------------------------------------------
// GN pass 1: per-(b,group) mean / inv-std
// ---------------------------------------------------------------------------
__global__ void gn_stats(const float* __restrict__ x, float2* __restrict__ stats)
{
    int b = blockIdx.x >> 5, g = blockIdx.x & 31;
    const float4* xp = (const float4*)(x + ((size_t)b * 512 + g * 16) * LQ);
    int tid = threadIdx.x;
    float s = 0.f, ss = 0.f;
    for (int i = tid; i < 4096; i += 256) {
        float4 v = xp[i];
        s  += v.x + v.y + v.z + v.w;
        ss += v.x * v.x + v.y * v.y + v.z * v.z + v.w * v.w;
    }
    __shared__ float rs[8], rss[8];
#pragma unroll
    for (int o = 16; o > 0; o >>= 1) {
        s  += __shfl_xor_sync(0xffffffffu, s, o);
        ss += __shfl_xor_sync(0xffffffffu, ss, o);
    }
    if ((tid & 31) == 0) { rs[tid >> 5] = s; rss[tid >> 5] = ss; }
    __syncthreads();
    if (tid == 0) {
        float S = 0.f, SS = 0.f;
#pragma unroll
        for (int i = 0; i < 8; i++) { S += rs[i]; SS += rss[i]; }
        float mean = S * (1.f / 16384.f);
        float var  = SS * (1.f / 16384.f) - mean * mean;
        stats[blockIdx.x] = make_float2(mean, rsqrtf(var + 1e-5f));
    }
}

// GN pass 2: normalize + transpose + split -> gnT hi/lo [b][l][c]
__global__ void gn_tsplit(const float* __restrict__ x, const float2* __restrict__ stats,
                          const float* __restrict__ w, const float* __restrict__ bb,
                          __nv_bfloat16* __restrict__ dhi, __nv_bfloat16* __restrict__ dlo)
{
    __shared__ float t[32][33];
    const int b = blockIdx.z;
    const int c0 = blockIdx.y * 32, l0 = blockIdx.x * 32;
    const int tx = threadIdx.x, ty = threadIdx.y;
#pragma unroll
    for (int k = 0; k < 32; k += 8)
        t[ty + k][tx] = x[((size_t)b * 512 + c0 + ty + k) * LQ + l0 + tx];
    __syncthreads();
    const int c = c0 + tx;
    float2 st = stats[b * 32 + (c >> 4)];
    const float wc = w[c] * st.y;
    const float bc = bb[c] - st.x * wc;
#pragma unroll
    for (int k = 0; k < 32; k += 8) {
        float v = t[tx][ty + k] * wc + bc;
        __nv_bfloat16 h = __float2bfloat16(v);
        __nv_bfloat16 l = __float2bfloat16(v - __bfloat162float(h));
        size_t o = ((size_t)b * 1024 + l0 + ty + k) * 512 + c;
        dhi[o] = h;
        dlo[o] = l;
    }
}

// Weight split
__global__ void wsplit_kernel(const float* __restrict__ w,
                              __nv_bfloat16* __restrict__ hi, __nv_bfloat16* __restrict__ lo)
{
    int i = blockIdx.x * 256 + threadIdx.x;
    float4 v = ((const float4*)w)[i];
    uint32_t h0, l0, h1, l1;
    split2(make_float2(v.x, v.y), h0, l0);
    split2(make_float2(v.z, v.w), h1, l1);
    ((uint2*)hi)[i] = make_uint2(h0, h1);
    ((uint2*)lo)[i] = make_uint2(l0, l1);
}

// ---------------------------------------------------------------------------
// GEMM core, pre-split operands, cp.async 2-stage pipeline.
// acc += A(BM x K).B(BN x K)^T, 3-product. 256 threads, stride 40.
// ---------------------------------------------------------------------------
template<int BM, int BN, int WM, int WN>
__device__ __forceinline__ void gemm_core(
    const __nv_bfloat16* __restrict__ Agh, const __nv_bfloat16* __restrict__ Agl, int lda,
    const __nv_bfloat16* __restrict__ Bgh, const __nv_bfloat16* __restrict__ Bgl, int ldb,
    int K, __nv_bfloat16* smem, float (*acc)[WN / 8][4])
{
    constexpr int ST = 40;
    constexpr int STAGE = (BM + BN) * 2 * ST;        // elements per stage
    constexpr int MT = WM / 16, NT = WN / 8;
    constexpr int WARPS_N = BN / WN;

    const int tid  = threadIdx.x;
    const int lane = tid & 31, warp = tid >> 5;
    const int wm = (warp / WARPS_N) * WM;
    const int wn = (warp % WARPS_N) * WN;
    const int g  = lane >> 2, t2 = (lane & 3) * 2;
    const uint32_t sb = smem_u32(smem);

    auto fill = [&](int stage, int k0) {
        const uint32_t base = sb + (uint32_t)stage * STAGE * 2;
#pragma unroll
        for (int i = tid; i < BM * 4; i += 256) {
            int r = i >> 2, s = (i & 3) * 8;
            uint32_t d = base + (uint32_t)(r * ST + s) * 2;
            cp16(d,                Agh + (size_t)r * lda + k0 + s);
            cp16(d + BM * ST * 2,  Agl + (size_t)r * lda + k0 + s);
        }
#pragma unroll
        for (int i = tid; i < BN * 4; i += 256) {
            int r = i >> 2, s = (i & 3) * 8;
            uint32_t d = base + 2 * BM * ST * 2 + (uint32_t)(r * ST + s) * 2;
            cp16(d,                Bgh + (size_t)r * ldb + k0 + s);
            cp16(d + BN * ST * 2,  Bgl + (size_t)r * ldb + k0 + s);
        }
    };

    const int NK = K / 32;
    fill(0, 0);
    CP_COMMIT();
    int buf = 0;
    for (int it = 0; it < NK; it++) {
        if (it + 1 < NK) fill(buf ^ 1, (it + 1) * 32);
        CP_COMMIT();
        CP_WAIT1();
        __syncthreads();
        const __nv_bfloat16* S0  = smem + buf * STAGE;
        const __nv_bfloat16* Ahi = S0;
        const __nv_bfloat16* Alo = S0 + BM * ST;
        const __nv_bfloat16* Bhi = S0 + 2 * BM * ST;
        const __nv_bfloat16* Blo = Bhi + BN * ST;
#pragma unroll
        for (int kk = 0; kk < 32; kk += 16) {
            uint32_t ahi[MT][4], alo[MT][4], bhi[NT][2], blo[NT][2];
#pragma unroll
            for (int im = 0; im < MT; im++) {
                const int off = (wm + im * 16 + g) * ST + kk + t2;
                ahi[im][0] = *(const uint32_t*)(Ahi + off);
                ahi[im][1] = *(const uint32_t*)(Ahi + off + 8 * ST);
                ahi[im][2] = *(const uint32_t*)(Ahi + off + 8);
                ahi[im][3] = *(const uint32_t*)(Ahi + off + 8 * ST + 8);
                alo[im][0] = *(const uint32_t*)(Alo + off);
                alo[im][1] = *(const uint32_t*)(Alo + off + 8 * ST);
                alo[im][2] = *(const uint32_t*)(Alo + off + 8);
                alo[im][3] = *(const uint32_t*)(Alo + off + 8 * ST + 8);
            }
#pragma unroll
            for (int in = 0; in < NT; in++) {
                const int off = (wn + in * 8 + g) * ST + kk + t2;
                bhi[in][0] = *(const uint32_t*)(Bhi + off);
                bhi[in][1] = *(const uint32_t*)(Bhi + off + 8);
                blo[in][0] = *(const uint32_t*)(Blo + off);
                blo[in][1] = *(const uint32_t*)(Blo + off + 8);
            }
#pragma unroll
            for (int im = 0; im < MT; im++)
#pragma unroll
                for (int in = 0; in < NT; in++) {
                    mma16816(acc[im][in], ahi[im], bhi[in]);
                    mma16816(acc[im][in], ahi[im], blo[in]);
                    mma16816(acc[im][in], alo[im], bhi[in]);
                }
        }
        __syncthreads();
        buf ^= 1;
    }
}

// qkv: [b][l][o] = gnT . W^T + bias, split output, q pre-scaled 1/8
__global__ __launch_bounds__(256)
void qkv_mma(const __nv_bfloat16* __restrict__ gh, const __nv_bfloat16* __restrict__ gl,
             const __nv_bfloat16* __restrict__ wh, const __nv_bfloat16* __restrict__ wl,
             const float* __restrict__ bias,
             __nv_bfloat16* __restrict__ qh, __nv_bfloat16* __restrict__ ql)
{
    extern __shared__ __nv_bfloat16 smem[];
    float acc[4][4][4] = {};
    const int m0 = blockIdx.x * 128, n0 = blockIdx.y * 128, b = blockIdx.z;
    gemm_core<128, 128, 64, 32>(gh + ((size_t)b * 1024 + m0) * 512,
                                gl + ((size_t)b * 1024 + m0) * 512, 512,
                                wh + (size_t)n0 * 512, wl + (size_t)n0 * 512, 512,
                                512, smem, acc);
    const int lane = threadIdx.x & 31, warp = threadIdx.x >> 5;
    const int wm = (warp / 4) * 64, wn = (warp % 4) * 32;
    const int g = lane >> 2, t2 = (lane & 3) * 2;
#pragma unroll
    for (int in = 0; in < 4; in++) {
        const int c = n0 + wn + in * 8 + t2;
        const float sc = ((c % 192) < 64) ? 0.125f : 1.f;
        const float bx = bias[c] * sc, by = bias[c + 1] * sc;
#pragma unroll
        for (int im = 0; im < 4; im++) {
            const int r = m0 + wm + im * 16 + g;
            size_t o0 = ((size_t)b * 1024 + r) * 1536 + c;
            size_t o1 = o0 + 8 * 1536;
            uint32_t h, l;
            split2(make_float2(acc[im][in][0] * sc + bx, acc[im][in][1] * sc + by), h, l);
            *(uint32_t*)(qh + o0) = h; *(uint32_t*)(ql + o0) = l;
            split2(make_float2(acc[im][in][2] * sc + bx, acc[im][in][3] * sc + by), h, l);
            *(uint32_t*)(qh + o1) = h; *(uint32_t*)(ql + o1) = l;
        }
    }
}

// out[b][co][l] = x + projW . aT^T + bias
__global__ __launch_bounds__(256)
void proj_mma(const __nv_bfloat16* __restrict__ wh, const __nv_bfloat16* __restrict__ wl,
              const __nv_bfloat16* __restrict__ ah, const __nv_bfloat16* __restrict__ al,
              const float* __restrict__ bias, const float* __restrict__ x,
              float* __restrict__ out)
{
    extern __shared__ __nv_bfloat16 smem[];
    float acc[4][4][4] = {};
    const int m0 = blockIdx.x * 128, n0 = blockIdx.y * 128, b = blockIdx.z;
    gemm_core<128, 128, 64, 32>(wh + (size_t)m0 * 512, wl + (size_t)m0 * 512, 512,
                                ah + ((size_t)b * 1024 + n0) * 512,
                                al + ((size_t)b * 1024 + n0) * 512, 512,
                                512, smem, acc);
    const int lane = threadIdx.x & 31, warp = threadIdx.x >> 5;
    const int wm = (warp / 4) * 64, wn = (warp % 4) * 32;
    const int g = lane >> 2, t2 = (lane & 3) * 2;
    const size_t bb = (size_t)b * 512 * 1024;
#pragma unroll
    for (int im = 0; im < 4; im++) {
        const int r = m0 + wm + im * 16 + g;
        const float bv0 = bias[r], bv1 = bias[r + 8];
#pragma unroll
        for (int in = 0; in < 4; in++) {
            const int c = n0 + wn + in * 8 + t2;
            size_t o0 = bb + (size_t)r * 1024 + c;
            size_t o1 = bb + (size_t)(r + 8) * 1024 + c;
            float2 x0 = *(const float2*)(x + o0);
            float2 x1 = *(const float2*)(x + o1);
            *(float2*)(out + o0) = make_float2(acc[im][in][0] + bv0 + x0.x,
                                               acc[im][in][1] + bv0 + x0.y);
            *(float2*)(out + o1) = make_float2(acc[im][in][2] + bv1 + x1.x,
                                               acc[im][in][3] + bv1 + x1.y);
        }
    }
}

// ---------------------------------------------------------------------------
// Fused flash attention, pre-split inputs, cp.async 2-stage K/V pipeline.
// 128 threads, 2 CTAs/SM. Q tile (128x64 hi/lo) in smem.
// ---------------------------------------------------------------------------
__global__ __launch_bounds__(128, 2)
void flash_kernel(const __nv_bfloat16* __restrict__ qkh,
                  const __nv_bfloat16* __restrict__ qkl,
                  __nv_bfloat16* __restrict__ aTh, __nv_bfloat16* __restrict__ aTl)
{
    constexpr int KP   = 72;
    constexpr int QSZ  = 128 * KP;          // elements
    constexpr int TSZ  = 64 * KP;           // elements
    constexpr int TSZB = TSZ * 2;           // bytes
    constexpr uint32_t QOFFB = 2 * QSZ * 2; // bytes (Qhi + Qlo)
    extern __shared__ __nv_bfloat16 sm[];
    __nv_bfloat16* Qhi = sm;
    __nv_bfloat16* Qlo = sm + QSZ;

    const int tid = threadIdx.x, lane = tid & 31, warp = tid >> 5;
    const int g = lane >> 2, t2 = (lane & 3) * 2;
    const int t0 = blockIdx.x * 128, bh = blockIdx.y;
    const int b = bh >> 3, h = bh & 7;
    const __nv_bfloat16* bh_hi = qkh + (size_t)b * 1024 * 1536 + h * 192;
    const __nv_bfloat16* bh_lo = qkl + (size_t)b * 1024 * 1536 + h * 192;

    const uint32_t sb = smem_u32(sm);
    const int sel = lane >> 3;
    const uint32_t kb0 = sb + QOFFB + (sel < 2 ? 0u : (uint32_t)TSZB)
                       + ((lane & 7) * KP + (sel & 1) * 8) * 2;
    const uint32_t vb0 = sb + QOFFB + 2 * TSZB + (sel < 2 ? 0u : (uint32_t)TSZB)
                       + (((sel & 1) * 8 + (lane & 7)) * KP) * 2;
    const uint32_t qbase = sb + ((warp * 32 + (lane & 15)) * KP + (lane >> 4) * 8) * 2;

    // K/V async fill for one stage (Khi,Klo,Vhi,Vlo each TSZB, contiguous)
    auto fill_kv = [&](int stage, int s0) {
        const uint32_t kst = sb + QOFFB + (uint32_t)stage * 4 * TSZB;
#pragma unroll
        for (int j = 0; j < 4; j++) {
            int i = tid + j * 128;
            int r = i >> 3, s = (i & 7) * 8;
            const size_t src = (size_t)(s0 + r) * 1536 + 64 + s;
            uint32_t doff = (uint32_t)(r * KP + s) * 2;
            cp16(kst + doff,            bh_hi + src);
            cp16(kst + TSZB + doff,     bh_lo + src);
            cp16(kst + 2 * TSZB + doff, bh_hi + src + 64);
            cp16(kst + 3 * TSZB + doff, bh_lo + src + 64);
        }
    };

    // --- fill Q tile once (synchronous copies) ---
#pragma unroll
    for (int j = 0; j < 8; j++) {
        int i = tid + j * 128;
        int r = i >> 3, s = (i & 7) * 8;
        const size_t src = (size_t)(t0 + r) * 1536 + s;
        *(uint4*)(Qhi + r * KP + s) = *(const uint4*)(bh_hi + src);
        *(uint4*)(Qlo + r * KP + s) = *(const uint4*)(bh_lo + src);
    }

    float mrow[2][2], lrow[2][2];
#pragma unroll
    for (int im = 0; im < 2; im++) {
        mrow[im][0] = mrow[im][1] = -1e30f;
        lrow[im][0] = lrow[im][1] = 0.f;
    }
    float O[2][8][4] = {};

    fill_kv(0, 0);
    CP_COMMIT();
    int buf = 0;
    for (int it = 0; it < 16; it++) {
        if (it + 1 < 16) fill_kv(buf ^ 1, (it + 1) * 64);
        CP_COMMIT();
        CP_WAIT1();
        __syncthreads();
        const uint32_t soff = (uint32_t)buf * 4 * TSZB;

        // --- S = Q . K^T ---
        float S[2][8][4] = {};
#pragma unroll
        for (int kc = 0; kc < 4; kc++) {
            uint32_t qhf[2][4], qlf[2][4];
#pragma unroll
            for (int im = 0; im < 2; im++) {
                uint32_t a = qbase + im * (16 * KP * 2) + kc * 32;
                ldsm_x4(qhf[im], a);
                ldsm_x4(qlf[im], a + QSZ * 2);
            }
#pragma unroll
            for (int in = 0; in < 8; in++) {
                uint32_t kb[4];
                ldsm_x4(kb, kb0 + soff + in * (8 * KP * 2) + kc * 32);
#pragma unroll
                for (int im = 0; im < 2; im++) {
                    mma16816(S[im][in], qhf[im], kb);
                    mma16816(S[im][in], qhf[im], kb + 2);
                    mma16816(S[im][in], qlf[im], kb);
                }
            }
        }

        // --- online softmax ---
#pragma unroll
        for (int im = 0; im < 2; im++) {
            float mx0 = -1e30f, mx1 = -1e30f;
#pragma unroll
            for (int in = 0; in < 8; in++) {
                mx0 = fmaxf(mx0, fmaxf(S[im][in][0], S[im][in][1]));
                mx1 = fmaxf(mx1, fmaxf(S[im][in][2], S[im][in][3]));
            }
            mx0 = fmaxf(mx0, __shfl_xor_sync(0xffffffffu, mx0, 1));
            mx0 = fmaxf(mx0, __shfl_xor_sync(0xffffffffu, mx0, 2));
            mx1 = fmaxf(mx1, __shfl_xor_sync(0xffffffffu, mx1, 1));
            mx1 = fmaxf(mx1, __shfl_xor_sync(0xffffffffu, mx1, 2));
            float nm0 = fmaxf(mrow[im][0], mx0), nm1 = fmaxf(mrow[im][1], mx1);
            float al0 = __expf(mrow[im][0] - nm0), al1 = __expf(mrow[im][1] - nm1);
            mrow[im][0] = nm0; mrow[im][1] = nm1;
            float sa = 0.f, sb2 = 0.f;
#pragma unroll
            for (int in = 0; in < 8; in++) {
                S[im][in][0] = __expf(S[im][in][0] - nm0);
                S[im][in][1] = __expf(S[im][in][1] - nm0);
                S[im][in][2] = __expf(S[im][in][2] - nm1);
                S[im][in][3] = __expf(S[im][in][3] - nm1);
                sa  += S[im][in][0] + S[im][in][1];
                sb2 += S[im][in][2] + S[im][in][3];
            }
            sa  += __shfl_xor_sync(0xffffffffu, sa, 1);
            sa  += __shfl_xor_sync(0xffffffffu, sa, 2);
            sb2 += __shfl_xor_sync(0xffffffffu, sb2, 1);
            sb2 += __shfl_xor_sync(0xffffffffu, sb2, 2);
            lrow[im][0] = lrow[im][0] * al0 + sa;
            lrow[im][1] = lrow[im][1] * al1 + sb2;
#pragma unroll
            for (int nt = 0; nt < 8; nt++) {
                O[im][nt][0] *= al0; O[im][nt][1] *= al0;
                O[im][nt][2] *= al1; O[im][nt][3] *= al1;
            }
        }

        // --- O += P . V ---
#pragma unroll
        for (int ks = 0; ks < 4; ks++) {
            uint32_t phi[2][4], plo[2][4];
#pragma unroll
            for (int im = 0; im < 2; im++) {
                split2(make_float2(S[im][2*ks][0],   S[im][2*ks][1]),   phi[im][0], plo[im][0]);
                split2(make_float2(S[im][2*ks][2],   S[im][2*ks][3]),   phi[im][1], plo[im][1]);
                split2(make_float2(S[im][2*ks+1][0], S[im][2*ks+1][1]), phi[im][2], plo[im][2]);
                split2(make_float2(S[im][2*ks+1][2], S[im][2*ks+1][3]), phi[im][3], plo[im][3]);
            }
#pragma unroll
            for (int nt = 0; nt < 8; nt++) {
                uint32_t vb[4];
                ldsm_x4_t(vb, vb0 + soff + ks * (16 * KP * 2) + nt * 16);
#pragma unroll
                for (int im = 0; im < 2; im++) {
                    mma16816(O[im][nt], phi[im], vb);
                    mma16816(O[im][nt], phi[im], vb + 2);
                    mma16816(O[im][nt], plo[im], vb);
                }
            }
        }
        __syncthreads();
        buf ^= 1;
    }

    // --- epilogue: write aT hi/lo ---
    __nv_bfloat16* oh = aTh + (size_t)b * 1024 * 512 + h * 64;
    __nv_bfloat16* ol = aTl + (size_t)b * 1024 * 512 + h * 64;
#pragma unroll
    for (int im = 0; im < 2; im++) {
        const float inv0 = 1.f / lrow[im][0], inv1 = 1.f / lrow[im][1];
        const int r0 = t0 + warp * 32 + im * 16 + g;
#pragma unroll
        for (int nt = 0; nt < 8; nt++) {
            const int c = nt * 8 + t2;
            size_t o0 = (size_t)r0 * 512 + c;
            size_t o1 = o0 + 8 * 512;
            uint32_t hh, ll;
            split2(make_float2(O[im][nt][0] * inv0, O[im][nt][1] * inv0), hh, ll);
            *(uint32_t*)(oh + o0) = hh; *(uint32_t*)(ol + o0) = ll;
            split2(make_float2(O[im][nt][2] * inv1, O[im][nt][3] * inv1), hh, ll);
            *(uint32_t*)(oh + o1) = hh; *(uint32_t*)(ol + o1) = ll;
        }
    }
}

// ---------------------------------------------------------------------------
extern "C" void kernel_launch(void* const* d_in, const int* in_sizes, int n_in,
                              void* d_out, int out_size)
{
    const float* x      = (const float*)d_in[0];
    const float* gn_w   = (const float*)d_in[1];
    const float* gn_b   = (const float*)d_in[2];
    const float* qkv_w  = (const float*)d_in[3];
    const float* qkv_b  = (const float*)d_in[4];
    const float* proj_w = (const float*)d_in[5];
    const float* proj_b = (const float*)d_in[6];
    float* out = (float*)d_out;

    float2* stats;
    __nv_bfloat16 *gh, *gl, *wqh, *wql, *wph, *wpl, *qh, *ql, *ah, *al;
    cudaGetSymbolAddress((void**)&stats, g_stats);
    cudaGetSymbolAddress((void**)&gh,  g_gnT_hi);
    cudaGetSymbolAddress((void**)&gl,  g_gnT_lo);
    cudaGetSymbolAddress((void**)&wqh, g_wq_hi);
    cudaGetSymbolAddress((void**)&wql, g_wq_lo);
    cudaGetSymbolAddress((void**)&wph, g_wp_hi);
    cudaGetSymbolAddress((void**)&wpl, g_wp_lo);
    cudaGetSymbolAddress((void**)&qh,  g_qkv_hi);
    cudaGetSymbolAddress((void**)&ql,  g_qkv_lo);
    cudaGetSymbolAddress((void**)&ah,  g_aT_hi);
    cudaGetSymbolAddress((void**)&al,  g_aT_lo);

    const int GEMM_SMEM  = 2 * (128 + 128) * 2 * 40 * 2;            // 81920 B
    const int FLASH_SMEM = (2 * 128 * 72) * 2 + 2 * 4 * 64 * 72 * 2; // 110592 B
    cudaFuncSetAttribute(qkv_mma,  cudaFuncAttributeMaxDynamicSharedMemorySize, GEMM_SMEM);
    cudaFuncSetAttribute(proj_mma, cudaFuncAttributeMaxDynamicSharedMemorySize, GEMM_SMEM);
    cudaFuncSetAttribute(flash_kernel, cudaFuncAttributeMaxDynamicSharedMemorySize,
                         FLASH_SMEM);

    wsplit_kernel<<<768, 256>>>(qkv_w, wqh, wql);
    wsplit_kernel<<<256, 256>>>(proj_w, wph, wpl);
    gn_stats<<<256, 256>>>(x, stats);
    gn_tsplit<<<dim3(32, 16, 8), dim3(32, 8)>>>(x, stats, gn_w, gn_b, gh, gl);
    qkv_mma<<<dim3(8, 12, 8), 256, GEMM_SMEM>>>(gh, gl, wqh, wql, qkv_b, qh, ql);
    flash_kernel<<<dim3(8, 64), 128, FLASH_SMEM>>>(qh, ql, ah, al);
    proj_mma<<<dim3(4, 8, 8), 256, GEMM_SMEM>>>(wph, wpl, ah, al, proj_b, x, out);
}

// round 10
// speedup vs baseline: 4.1341x; 1.0073x over previous
#include <cuda_runtime.h>
#include <cuda_bf16.h>
#include <cstdint>

#define LQ 1024
// B=8, C=512, heads=8/batch (bh=64), ch=64, groups=32

// ---------------------------------------------------------------------------
// Scratch (all GEMM operands pre-split bf16 hi/lo)
// ---------------------------------------------------------------------------
__device__ float2 g_stats[8 * 32];
__device__ __nv_bfloat16 g_gnT_hi[(size_t)8 * 1024 * 512];
__device__ __nv_bfloat16 g_gnT_lo[(size_t)8 * 1024 * 512];
__device__ __nv_bfloat16 g_wq_hi[1536 * 512];
__device__ __nv_bfloat16 g_wq_lo[1536 * 512];
__device__ __nv_bfloat16 g_wp_hi[512 * 512];
__device__ __nv_bfloat16 g_wp_lo[512 * 512];
__device__ __nv_bfloat16 g_qkv_hi[(size_t)8 * 1024 * 1536];  // q pre-scaled 1/8
__device__ __nv_bfloat16 g_qkv_lo[(size_t)8 * 1024 * 1536];
__device__ __nv_bfloat16 g_aT_hi[(size_t)8 * 1024 * 512];
__device__ __nv_bfloat16 g_aT_lo[(size_t)8 * 1024 * 512];

// ---------------------------------------------------------------------------
// helpers
// ---------------------------------------------------------------------------
__device__ __forceinline__ void split2(float2 f, uint32_t& hi, uint32_t& lo)
{
    __nv_bfloat162 h = __float22bfloat162_rn(f);
    float2 rem = make_float2(f.x - __bfloat162float(h.x),
                             f.y - __bfloat162float(h.y));
    __nv_bfloat162 l = __float22bfloat162_rn(rem);
    hi = *reinterpret_cast<uint32_t*>(&h);
    lo = *reinterpret_cast<uint32_t*>(&l);
}

__device__ __forceinline__ void mma16816(float* c, const uint32_t* a, const uint32_t* b)
{
    asm volatile(
        "mma.sync.aligned.m16n8k16.row.col.f32.bf16.bf16.f32 "
        "{%0,%1,%2,%3}, {%4,%5,%6,%7}, {%8,%9}, {%0,%1,%2,%3};"
        : "+f"(c[0]), "+f"(c[1]), "+f"(c[2]), "+f"(c[3])
        : "r"(a[0]), "r"(a[1]), "r"(a[2]), "r"(a[3]), "r"(b[0]), "r"(b[1]));
}

__device__ __forceinline__ uint32_t smem_u32(const void* p)
{
    uint32_t a;
    asm("{ .reg .u64 t; cvta.to.shared.u64 t, %1; cvt.u32.u64 %0, t; }" : "=r"(a) : "l"(p));
    return a;
}

__device__ __forceinline__ void ldsm_x4(uint32_t* r, uint32_t addr)
{
    asm volatile("ldmatrix.sync.aligned.m8n8.x4.shared.b16 {%0,%1,%2,%3}, [%4];"
                 : "=r"(r[0]), "=r"(r[1]), "=r"(r[2]), "=r"(r[3]) : "r"(addr));
}
__device__ __forceinline__ void ldsm_x4_t(uint32_t* r, uint32_t addr)
{
    asm volatile("ldmatrix.sync.aligned.m8n8.x4.trans.shared.b16 {%0,%1,%2,%3}, [%4];"
                 : "=r"(r[0]), "=r"(r[1]), "=r"(r[2]), "=r"(r[3]) : "r"(addr));
}

__device__ __forceinline__ void cp16(uint32_t dst, const void* src)
{
    asm volatile("cp.async.cg.shared.global [%0], [%1], 16;" :: "r"(dst), "l"(src));
}
#define CP_COMMIT() asm volatile("cp.async.commit_group;" ::: "memory")
#define CP_WAIT1()  asm volatile("cp.async.wait_group 1;" ::: "memory")

// ---------------------------------------------------------------------------
// GN pass 1: per-(b,group) mean / inv-std
// ---------------------------------------------------------------------------
__global__ void gn_stats(const float* __restrict__ x, float2* __restrict__ stats)
{
    int b = blockIdx.x >> 5, g = blockIdx.x & 31;
    const float4* xp = (const float4*)(x + ((size_t)b * 512 + g * 16) * LQ);
    int tid = threadIdx.x;
    float s = 0.f, ss = 0.f;
    for (int i = tid; i < 4096; i += 256) {
        float4 v = xp[i];
        s  += v.x + v.y + v.z + v.w;
        ss += v.x * v.x + v.y * v.y + v.z * v.z + v.w * v.w;
    }
    __shared__ float rs[8], rss[8];
#pragma unroll
    for (int o = 16; o > 0; o >>= 1) {
        s  += __shfl_xor_sync(0xffffffffu, s, o);
        ss += __shfl_xor_sync(0xffffffffu, ss, o);
    }
    if ((tid & 31) == 0) { rs[tid >> 5] = s; rss[tid >> 5] = ss; }
    __syncthreads();
    if (tid == 0) {
        float S = 0.f, SS = 0.f;
#pragma unroll
        for (int i = 0; i < 8; i++) { S += rs[i]; SS += rss[i]; }
        float mean = S * (1.f / 16384.f);
        float var  = SS * (1.f / 16384.f) - mean * mean;
        stats[blockIdx.x] = make_float2(mean, rsqrtf(var + 1e-5f));
    }
}

// GN pass 2: normalize + transpose + split -> gnT hi/lo [b][l][c]
__global__ void gn_tsplit(const float* __restrict__ x, const float2* __restrict__ stats,
                          const float* __restrict__ w, const float* __restrict__ bb,
                          __nv_bfloat16* __restrict__ dhi, __nv_bfloat16* __restrict__ dlo)
{
    __shared__ float t[32][33];
    const int b = blockIdx.z;
    const int c0 = blockIdx.y * 32, l0 = blockIdx.x * 32;
    const int tx = threadIdx.x, ty = threadIdx.y;
#pragma unroll
    for (int k = 0; k < 32; k += 8)
        t[ty + k][tx] = x[((size_t)b * 512 + c0 + ty + k) * LQ + l0 + tx];
    __syncthreads();
    const int c = c0 + tx;
    float2 st = stats[b * 32 + (c >> 4)];
    const float wc = w[c] * st.y;
    const float bc = bb[c] - st.x * wc;
#pragma unroll
    for (int k = 0; k < 32; k += 8) {
        float v = t[tx][ty + k] * wc + bc;
        __nv_bfloat16 h = __float2bfloat16(v);
        __nv_bfloat16 l = __float2bfloat16(v - __bfloat162float(h));
        size_t o = ((size_t)b * 1024 + l0 + ty + k) * 512 + c;
        dhi[o] = h;
        dlo[o] = l;
    }
}

// Weight split
__global__ void wsplit_kernel(const float* __restrict__ w,
                              __nv_bfloat16* __restrict__ hi, __nv_bfloat16* __restrict__ lo)
{
    int i = blockIdx.x * 256 + threadIdx.x;
    float4 v = ((const float4*)w)[i];
    uint32_t h0, l0, h1, l1;
    split2(make_float2(v.x, v.y), h0, l0);
    split2(make_float2(v.z, v.w), h1, l1);
    ((uint2*)hi)[i] = make_uint2(h0, h1);
    ((uint2*)lo)[i] = make_uint2(l0, l1);
}

// ---------------------------------------------------------------------------
// GEMM core, pre-split operands, cp.async 2-stage pipeline, ldmatrix frags.
// acc += A(BM x K).B(BN x K)^T, 3-product. 256 threads, stride 40.
// ---------------------------------------------------------------------------
template<int BM, int BN, int WM, int WN>
__device__ __forceinline__ void gemm_core(
    const __nv_bfloat16* __restrict__ Agh, const __nv_bfloat16* __restrict__ Agl, int lda,
    const __nv_bfloat16* __restrict__ Bgh, const __nv_bfloat16* __restrict__ Bgl, int ldb,
    int K, __nv_bfloat16* smem, float (*acc)[WN / 8][4])
{
    constexpr int ST = 40;
    constexpr int STAGE = (BM + BN) * 2 * ST;          // elements per stage
    constexpr uint32_t STAGEB = STAGE * 2;             // bytes
    constexpr int MT = WM / 16, NT = WN / 8;
    constexpr int WARPS_N = BN / WN;

    const int tid  = threadIdx.x;
    const int lane = tid & 31, warp = tid >> 5;
    const int wm = (warp / WARPS_N) * WM;
    const int wn = (warp % WARPS_N) * WN;
    const int sel = lane >> 3;
    const uint32_t sb = smem_u32(smem);

    // per-lane ldmatrix base offsets (within a stage, bytes)
    // A: x4 = 16x16 tile; lanes 0-15 rows, 16-31 rows at col+8
    const uint32_t aoff = (uint32_t)((wm + (lane & 15)) * ST + (lane >> 4) * 8) * 2;
    // B: x4 = n8 tile, m0/m1 hi (cols 0,8), m2/m3 lo
    const uint32_t boff = (uint32_t)(2 * BM * ST * 2)
                        + (sel < 2 ? 0u : (uint32_t)(BN * ST * 2))
                        + (uint32_t)((wn + (lane & 7)) * ST + (sel & 1) * 8) * 2;

    auto fill = [&](int stage, int k0) {
        const uint32_t base = sb + (uint32_t)stage * STAGEB;
#pragma unroll
        for (int i = tid; i < BM * 4; i += 256) {
            int r = i >> 2, s = (i & 3) * 8;
            uint32_t d = base + (uint32_t)(r * ST + s) * 2;
            cp16(d,                Agh + (size_t)r * lda + k0 + s);
            cp16(d + BM * ST * 2,  Agl + (size_t)r * lda + k0 + s);
        }
#pragma unroll
        for (int i = tid; i < BN * 4; i += 256) {
            int r = i >> 2, s = (i & 3) * 8;
            uint32_t d = base + 2 * BM * ST * 2 + (uint32_t)(r * ST + s) * 2;
            cp16(d,                Bgh + (size_t)r * ldb + k0 + s);
            cp16(d + BN * ST * 2,  Bgl + (size_t)r * ldb + k0 + s);
        }
    };

    const int NK = K / 32;
    fill(0, 0);
    CP_COMMIT();
    int buf = 0;
    for (int it = 0; it < NK; it++) {
        if (it + 1 < NK) fill(buf ^ 1, (it + 1) * 32);
        CP_COMMIT();
        CP_WAIT1();
        __syncthreads();
        const uint32_t abase = sb + (uint32_t)buf * STAGEB + aoff;
        const uint32_t bbase = sb + (uint32_t)buf * STAGEB + boff;
#pragma unroll
        for (int kk = 0; kk < 32; kk += 16) {
            uint32_t ahi[MT][4], alo[MT][4], bfr[NT][4];
#pragma unroll
            for (int im = 0; im < MT; im++) {
                const uint32_t a = abase + im * (16 * ST * 2) + kk * 2;
                ldsm_x4(ahi[im], a);
                ldsm_x4(alo[im], a + BM * ST * 2);
            }
#pragma unroll
            for (int in = 0; in < NT; in++)
                ldsm_x4(bfr[in], bbase + in * (8 * ST * 2) + kk * 2);
#pragma unroll
            for (int im = 0; im < MT; im++)
#pragma unroll
                for (int in = 0; in < NT; in++) {
                    mma16816(acc[im][in], ahi[im], bfr[in]);       // hi.hi
                    mma16816(acc[im][in], ahi[im], bfr[in] + 2);   // hi.lo
                    mma16816(acc[im][in], alo[im], bfr[in]);       // lo.hi
                }
        }
        __syncthreads();
        buf ^= 1;
    }
}

// qkv: [b][l][o] = gnT . W^T + bias, split output, q pre-scaled 1/8
__global__ __launch_bounds__(256)
void qkv_mma(const __nv_bfloat16* __restrict__ gh, const __nv_bfloat16* __restrict__ gl,
             const __nv_bfloat16* __restrict__ wh, const __nv_bfloat16* __restrict__ wl,
             const float* __restrict__ bias,
             __nv_bfloat16* __restrict__ qh, __nv_bfloat16* __restrict__ ql)
{
    extern __shared__ __nv_bfloat16 smem[];
    float acc[4][4][4] = {};
    const int m0 = blockIdx.x * 128, n0 = blockIdx.y * 128, b = blockIdx.z;
    gemm_core<128, 128, 64, 32>(gh + ((size_t)b * 1024 + m0) * 512,
                                gl + ((size_t)b * 1024 + m0) * 512, 512,
                                wh + (size_t)n0 * 512, wl + (size_t)n0 * 512, 512,
                                512, smem, acc);
    const int lane = threadIdx.x & 31, warp = threadIdx.x >> 5;
    const int wm = (warp / 4) * 64, wn = (warp % 4) * 32;
    const int g = lane >> 2, t2 = (lane & 3) * 2;
#pragma unroll
    for (int in = 0; in < 4; in++) {
        const int c = n0 + wn + in * 8 + t2;
        const float sc = ((c % 192) < 64) ? 0.125f : 1.f;
        const float bx = bias[c] * sc, by = bias[c + 1] * sc;
#pragma unroll
        for (int im = 0; im < 4; im++) {
            const int r = m0 + wm + im * 16 + g;
            size_t o0 = ((size_t)b * 1024 + r) * 1536 + c;
            size_t o1 = o0 + 8 * 1536;
            uint32_t h, l;
            split2(make_float2(acc[im][in][0] * sc + bx, acc[im][in][1] * sc + by), h, l);
            *(uint32_t*)(qh + o0) = h; *(uint32_t*)(ql + o0) = l;
            split2(make_float2(acc[im][in][2] * sc + bx, acc[im][in][3] * sc + by), h, l);
            *(uint32_t*)(qh + o1) = h; *(uint32_t*)(ql + o1) = l;
        }
    }
}

// out[b][co][l] = x + projW . aT^T + bias
__global__ __launch_bounds__(256)
void proj_mma(const __nv_bfloat16* __restrict__ wh, const __nv_bfloat16* __restrict__ wl,
              const __nv_bfloat16* __restrict__ ah, const __nv_bfloat16* __restrict__ al,
              const float* __restrict__ bias, const float* __restrict__ x,
              float* __restrict__ out)
{
    extern __shared__ __nv_bfloat16 smem[];
    float acc[4][4][4] = {};
    const int m0 = blockIdx.x * 128, n0 = blockIdx.y * 128, b = blockIdx.z;
    gemm_core<128, 128, 64, 32>(wh + (size_t)m0 * 512, wl + (size_t)m0 * 512, 512,
                                ah + ((size_t)b * 1024 + n0) * 512,
                                al + ((size_t)b * 1024 + n0) * 512, 512,
                                512, smem, acc);
    const int lane = threadIdx.x & 31, warp = threadIdx.x >> 5;
    const int wm = (warp / 4) * 64, wn = (warp % 4) * 32;
    const int g = lane >> 2, t2 = (lane & 3) * 2;
    const size_t bb = (size_t)b * 512 * 1024;
#pragma unroll
    for (int im = 0; im < 4; im++) {
        const int r = m0 + wm + im * 16 + g;
        const float bv0 = bias[r], bv1 = bias[r + 8];
#pragma unroll
        for (int in = 0; in < 4; in++) {
            const int c = n0 + wn + in * 8 + t2;
            size_t o0 = bb + (size_t)r * 1024 + c;
            size_t o1 = bb + (size_t)(r + 8) * 1024 + c;
            float2 x0 = *(const float2*)(x + o0);
            float2 x1 = *(const float2*)(x + o1);
            *(float2*)(out + o0) = make_float2(acc[im][in][0] + bv0 + x0.x,
                                               acc[im][in][1] + bv0 + x0.y);
            *(float2*)(out + o1) = make_float2(acc[im][in][2] + bv1 + x1.x,
                                               acc[im][in][3] + bv1 + x1.y);
        }
    }
}

// ---------------------------------------------------------------------------
// Fused flash attention, pre-split inputs, cp.async 2-stage K/V pipeline.
// 128 threads, 2 CTAs/SM. Q tile (128x64 hi/lo) in smem.
// ---------------------------------------------------------------------------
__global__ __launch_bounds__(128, 2)
void flash_kernel(const __nv_bfloat16* __restrict__ qkh,
                  const __nv_bfloat16* __restrict__ qkl,
                  __nv_bfloat16* __restrict__ aTh, __nv_bfloat16* __restrict__ aTl)
{
    constexpr int KP   = 72;
    constexpr int QSZ  = 128 * KP;
    constexpr int TSZ  = 64 * KP;
    constexpr int TSZB = TSZ * 2;
    constexpr uint32_t QOFFB = 2 * QSZ * 2;
    extern __shared__ __nv_bfloat16 sm[];
    __nv_bfloat16* Qhi = sm;
    __nv_bfloat16* Qlo = sm + QSZ;

    const int tid = threadIdx.x, lane = tid & 31, warp = tid >> 5;
    const int g = lane >> 2, t2 = (lane & 3) * 2;
    const int t0 = blockIdx.x * 128, bh = blockIdx.y;
    const int b = bh >> 3, h = bh & 7;
    const __nv_bfloat16* bh_hi = qkh + (size_t)b * 1024 * 1536 + h * 192;
    const __nv_bfloat16* bh_lo = qkl + (size_t)b * 1024 * 1536 + h * 192;

    const uint32_t sb = smem_u32(sm);
    const int sel = lane >> 3;
    const uint32_t kb0 = sb + QOFFB + (sel < 2 ? 0u : (uint32_t)TSZB)
                       + ((lane & 7) * KP + (sel & 1) * 8) * 2;
    const uint32_t vb0 = sb + QOFFB + 2 * TSZB + (sel < 2 ? 0u : (uint32_t)TSZB)
                       + (((sel & 1) * 8 + (lane & 7)) * KP) * 2;
    const uint32_t qbase = sb + ((warp * 32 + (lane & 15)) * KP + (lane >> 4) * 8) * 2;

    auto fill_kv = [&](int stage, int s0) {
        const uint32_t kst = sb + QOFFB + (uint32_t)stage * 4 * TSZB;
#pragma unroll
        for (int j = 0; j < 4; j++) {
            int i = tid + j * 128;
            int r = i >> 3, s = (i & 7) * 8;
            const size_t src = (size_t)(s0 + r) * 1536 + 64 + s;
            uint32_t doff = (uint32_t)(r * KP + s) * 2;
            cp16(kst + doff,            bh_hi + src);
            cp16(kst + TSZB + doff,     bh_lo + src);
            cp16(kst + 2 * TSZB + doff, bh_hi + src + 64);
            cp16(kst + 3 * TSZB + doff, bh_lo + src + 64);
        }
    };

    // --- fill Q tile once ---
#pragma unroll
    for (int j = 0; j < 8; j++) {
        int i = tid + j * 128;
        int r = i >> 3, s = (i & 7) * 8;
        const size_t src = (size_t)(t0 + r) * 1536 + s;
        *(uint4*)(Qhi + r * KP + s) = *(const uint4*)(bh_hi + src);
        *(uint4*)(Qlo + r * KP + s) = *(const uint4*)(bh_lo + src);
    }

    float mrow[2][2], lrow[2][2];
#pragma unroll
    for (int im = 0; im < 2; im++) {
        mrow[im][0] = mrow[im][1] = -1e30f;
        lrow[im][0] = lrow[im][1] = 0.f;
    }
    float O[2][8][4] = {};

    fill_kv(0, 0);
    CP_COMMIT();
    int buf = 0;
    for (int it = 0; it < 16; it++) {
        if (it + 1 < 16) fill_kv(buf ^ 1, (it + 1) * 64);
        CP_COMMIT();
        CP_WAIT1();
        __syncthreads();
        const uint32_t soff = (uint32_t)buf * 4 * TSZB;

        // --- S = Q . K^T ---
        float S[2][8][4] = {};
#pragma unroll
        for (int kc = 0; kc < 4; kc++) {
            uint32_t qhf[2][4], qlf[2][4];
#pragma unroll
            for (int im = 0; im < 2; im++) {
                uint32_t a = qbase + im * (16 * KP * 2) + kc * 32;
                ldsm_x4(qhf[im], a);
                ldsm_x4(qlf[im], a + QSZ * 2);
            }
#pragma unroll
            for (int in = 0; in < 8; in++) {
                uint32_t kb[4];
                ldsm_x4(kb, kb0 + soff + in * (8 * KP * 2) + kc * 32);
#pragma unroll
                for (int im = 0; im < 2; im++) {
                    mma16816(S[im][in], qhf[im], kb);
                    mma16816(S[im][in], qhf[im], kb + 2);
                    mma16816(S[im][in], qlf[im], kb);
                }
            }
        }

        // --- online softmax ---
#pragma unroll
        for (int im = 0; im < 2; im++) {
            float mx0 = -1e30f, mx1 = -1e30f;
#pragma unroll
            for (int in = 0; in < 8; in++) {
                mx0 = fmaxf(mx0, fmaxf(S[im][in][0], S[im][in][1]));
                mx1 = fmaxf(mx1, fmaxf(S[im][in][2], S[im][in][3]));
            }
            mx0 = fmaxf(mx0, __shfl_xor_sync(0xffffffffu, mx0, 1));
            mx0 = fmaxf(mx0, __shfl_xor_sync(0xffffffffu, mx0, 2));
            mx1 = fmaxf(mx1, __shfl_xor_sync(0xffffffffu, mx1, 1));
            mx1 = fmaxf(mx1, __shfl_xor_sync(0xffffffffu, mx1, 2));
            float nm0 = fmaxf(mrow[im][0], mx0), nm1 = fmaxf(mrow[im][1], mx1);
            float al0 = __expf(mrow[im][0] - nm0), al1 = __expf(mrow[im][1] - nm1);
            mrow[im][0] = nm0; mrow[im][1] = nm1;
            float sa = 0.f, sb2 = 0.f;
#pragma unroll
            for (int in = 0; in < 8; in++) {
                S[im][in][0] = __expf(S[im][in][0] - nm0);
                S[im][in][1] = __expf(S[im][in][1] - nm0);
                S[im][in][2] = __expf(S[im][in][2] - nm1);
                S[im][in][3] = __expf(S[im][in][3] - nm1);
                sa  += S[im][in][0] + S[im][in][1];
                sb2 += S[im][in][2] + S[im][in][3];
            }
            sa  += __shfl_xor_sync(0xffffffffu, sa, 1);
            sa  += __shfl_xor_sync(0xffffffffu, sa, 2);
            sb2 += __shfl_xor_sync(0xffffffffu, sb2, 1);
            sb2 += __shfl_xor_sync(0xffffffffu, sb2, 2);
            lrow[im][0] = lrow[im][0] * al0 + sa;
            lrow[im][1] = lrow[im][1] * al1 + sb2;
#pragma unroll
            for (int nt = 0; nt < 8; nt++) {
                O[im][nt][0] *= al0; O[im][nt][1] *= al0;
                O[im][nt][2] *= al1; O[im][nt][3] *= al1;
            }
        }

        // --- O += P . V ---
#pragma unroll
        for (int ks = 0; ks < 4; ks++) {
            uint32_t phi[2][4], plo[2][4];
#pragma unroll
            for (int im = 0; im < 2; im++) {
                split2(make_float2(S[im][2*ks][0],   S[im][2*ks][1]),   phi[im][0], plo[im][0]);
                split2(make_float2(S[im][2*ks][2],   S[im][2*ks][3]),   phi[im][1], plo[im][1]);
                split2(make_float2(S[im][2*ks+1][0], S[im][2*ks+1][1]), phi[im][2], plo[im][2]);
                split2(make_float2(S[im][2*ks+1][2], S[im][2*ks+1][3]), phi[im][3], plo[im][3]);
            }
#pragma unroll
            for (int nt = 0; nt < 8; nt++) {
                uint32_t vb[4];
                ldsm_x4_t(vb, vb0 + soff + ks * (16 * KP * 2) + nt * 16);
#pragma unroll
                for (int im = 0; im < 2; im++) {
                    mma16816(O[im][nt], phi[im], vb);
                    mma16816(O[im][nt], phi[im], vb + 2);
                    mma16816(O[im][nt], plo[im], vb);
                }
            }
        }
        __syncthreads();
        buf ^= 1;
    }

    // --- epilogue: write aT hi/lo ---
    __nv_bfloat16* oh = aTh + (size_t)b * 1024 * 512 + h * 64;
    __nv_bfloat16* ol = aTl + (size_t)b * 1024 * 512 + h * 64;
#pragma unroll
    for (int im = 0; im < 2; im++) {
        const float inv0 = 1.f / lrow[im][0], inv1 = 1.f / lrow[im][1];
        const int r0 = t0 + warp * 32 + im * 16 + g;
#pragma unroll
        for (int nt = 0; nt < 8; nt++) {
            const int c = nt * 8 + t2;
            size_t o0 = (size_t)r0 * 512 + c;
            size_t o1 = o0 + 8 * 512;
            uint32_t hh, ll;
            split2(make_float2(O[im][nt][0] * inv0, O[im][nt][1] * inv0), hh, ll);
            *(uint32_t*)(oh + o0) = hh; *(uint32_t*)(ol + o0) = ll;
            split2(make_float2(O[im][nt][2] * inv1, O[im][nt][3] * inv1), hh, ll);
            *(uint32_t*)(oh + o1) = hh; *(uint32_t*)(ol + o1) = ll;
        }
    }
}

// ---------------------------------------------------------------------------
extern "C" void kernel_launch(void* const* d_in, const int* in_sizes, int n_in,
                              void* d_out, int out_size)
{
    const float* x      = (const float*)d_in[0];
    const float* gn_w   = (const float*)d_in[1];
    const float* gn_b   = (const float*)d_in[2];
    const float* qkv_w  = (const float*)d_in[3];
    const float* qkv_b  = (const float*)d_in[4];
    const float* proj_w = (const float*)d_in[5];
    const float* proj_b = (const float*)d_in[6];
    float* out = (float*)d_out;

    float2* stats;
    __nv_bfloat16 *gh, *gl, *wqh, *wql, *wph, *wpl, *qh, *ql, *ah, *al;
    cudaGetSymbolAddress((void**)&stats, g_stats);
    cudaGetSymbolAddress((void**)&gh,  g_gnT_hi);
    cudaGetSymbolAddress((void**)&gl,  g_gnT_lo);
    cudaGetSymbolAddress((void**)&wqh, g_wq_hi);
    cudaGetSymbolAddress((void**)&wql, g_wq_lo);
    cudaGetSymbolAddress((void**)&wph, g_wp_hi);
    cudaGetSymbolAddress((void**)&wpl, g_wp_lo);
    cudaGetSymbolAddress((void**)&qh,  g_qkv_hi);
    cudaGetSymbolAddress((void**)&ql,  g_qkv_lo);
    cudaGetSymbolAddress((void**)&ah,  g_aT_hi);
    cudaGetSymbolAddress((void**)&al,  g_aT_lo);

    const int GEMM_SMEM  = 2 * (128 + 128) * 2 * 40 * 2;             // 81920 B
    const int FLASH_SMEM = (2 * 128 * 72) * 2 + 2 * 4 * 64 * 72 * 2; // 110592 B
    cudaFuncSetAttribute(qkv_mma,  cudaFuncAttributeMaxDynamicSharedMemorySize, GEMM_SMEM);
    cudaFuncSetAttribute(proj_mma, cudaFuncAttributeMaxDynamicSharedMemorySize, GEMM_SMEM);
    cudaFuncSetAttribute(flash_kernel, cudaFuncAttributeMaxDynamicSharedMemorySize,
                         FLASH_SMEM);

    wsplit_kernel<<<768, 256>>>(qkv_w, wqh, wql);
    wsplit_kernel<<<256, 256>>>(proj_w, wph, wpl);
    gn_stats<<<256, 256>>>(x, stats);
    gn_tsplit<<<dim3(32, 16, 8), dim3(32, 8)>>>(x, stats, gn_w, gn_b, gh, gl);
    qkv_mma<<<dim3(8, 12, 8), 256, GEMM_SMEM>>>(gh, gl, wqh, wql, qkv_b, qh, ql);
    flash_kernel<<<dim3(8, 64), 128, FLASH_SMEM>>>(qh, ql, ah, al);
    proj_mma<<<dim3(4, 8, 8), 256, GEMM_SMEM>>>(wph, wpl, ah, al, proj_b, x, out);
}